// round 2
// baseline (speedup 1.0000x reference)
#include <cuda_runtime.h>

#define Bsz 64
#define Lsz 500
#define Dsz 300
#define Fsz 100
#define IDs 32
#define BL  (Bsz*Lsz)   // 32000

// ---------------- scratch (static device globals; no allocation) ----------------
__device__ float g_eg[2][BL*Dsz];     // gated embeddings (B*L, 300) per side
__device__ float g_dots[2][BL*3];     // word-gate partial dots
__device__ float g_C[2][BL*300];      // GEMM out (B*L, 3F)
__device__ float g_ut[2][BL*Fsz];     // conv feature, layout (b,l,f)
__device__ float g_nrm[2][BL];        // per-(b,l) squared norms over F
__device__ float g_att[2][BL];        // attention row/col sums
__device__ float g_Wt[2][300*300];    // repacked doc-conv weights (d, k*F+f)

__device__ __forceinline__ float warpSum(float v) {
#pragma unroll
    for (int o = 16; o; o >>= 1) v += __shfl_down_sync(0xffffffffu, v, o);
    return v;
}

// ---------------- K0: repack doc-conv weights W[f,k,d] -> Wt[d, k*F+f] ----------------
__global__ void k_prep(const float* __restrict__ uw, const float* __restrict__ iw) {
    int idx = blockIdx.x * 256 + threadIdx.x;
    if (idx >= 300 * 300) return;
    int d = idx / 300, j = idx % 300;
    int k = j / Fsz, f = j % Fsz;
    g_Wt[0][idx] = uw[(f * 3 + k) * Dsz + d];
    g_Wt[1][idx] = iw[(f * 3 + k) * Dsz + d];
}

// ---------------- K1: gather embedding rows + 3 word-gate dots ----------------
__global__ void k_gather(const int* __restrict__ udoc, const int* __restrict__ idoc,
                         const float* __restrict__ uemb, const float* __restrict__ iemb,
                         const float* __restrict__ wc) {
    int side = blockIdx.y;
    int bl = blockIdx.x;
    const int* doc = side ? idoc : udoc;
    const float* emb = side ? iemb : uemb;
    int row = doc[bl];
    const float* e = emb + (size_t)row * Dsz;
    float* dst = g_eg[side] + (size_t)bl * Dsz;
    float p0 = 0.f, p1 = 0.f, p2 = 0.f;
    for (int d = threadIdx.x; d < Dsz; d += 128) {
        float v = e[d];
        dst[d] = v;
        p0 += v * wc[d];
        p1 += v * wc[Dsz + d];
        p2 += v * wc[2 * Dsz + d];
    }
    __shared__ float sh[3][4];
    p0 = warpSum(p0); p1 = warpSum(p1); p2 = warpSum(p2);
    int lane = threadIdx.x & 31, w = threadIdx.x >> 5;
    if (lane == 0) { sh[0][w] = p0; sh[1][w] = p1; sh[2][w] = p2; }
    __syncthreads();
    if (threadIdx.x == 0) {
        g_dots[side][bl * 3 + 0] = sh[0][0] + sh[0][1] + sh[0][2] + sh[0][3];
        g_dots[side][bl * 3 + 1] = sh[1][0] + sh[1][1] + sh[1][2] + sh[1][3];
        g_dots[side][bl * 3 + 2] = sh[2][0] + sh[2][1] + sh[2][2] + sh[2][3];
    }
}

// ---------------- K2: sigmoid gate from neighbor dots, scale rows in place ----------------
__global__ void k_gate(const float* __restrict__ wcb) {
    int side = blockIdx.y;
    int bl = blockIdx.x;
    int l = bl % Lsz;
    __shared__ float gsh;
    if (threadIdx.x == 0) {
        float g = g_dots[side][bl * 3 + 1] + wcb[0];
        if (l >= 1)       g += g_dots[side][(bl - 1) * 3 + 0];
        if (l <= Lsz - 2) g += g_dots[side][(bl + 1) * 3 + 2];
        gsh = 1.f / (1.f + __expf(-g));
    }
    __syncthreads();
    float gate = gsh;
    float* p = g_eg[side] + (size_t)bl * Dsz;
    for (int d = threadIdx.x; d < Dsz; d += 128) p[d] *= gate;
}

// ---------------- K3: GEMM (32000 x 300) @ (300 x 300) per side ----------------
// BM=128, BN=64, BK=16, 256 threads, 8x4 per thread
__global__ void k_gemm() {
    const int side = blockIdx.z;
    const float* __restrict__ A  = g_eg[side];
    const float* __restrict__ Bm = g_Wt[side];
    float* __restrict__ Cm = g_C[side];
    __shared__ float As[16][128];
    __shared__ float Bs[16][64];
    const int tid = threadIdx.x;
    const int tx = tid & 15, ty = tid >> 4;
    const int m0 = blockIdx.x * 128;
    const int n0 = blockIdx.y * 64;
    float acc[8][4];
#pragma unroll
    for (int i = 0; i < 8; i++)
#pragma unroll
        for (int j = 0; j < 4; j++) acc[i][j] = 0.f;

    const int a_row = tid >> 2;       // 0..63
    const int a_c4  = tid & 3;        // 0..3
    const int b_kk  = tid >> 4;       // 0..15
    const int b_nn  = (tid & 15) * 4; // 0..60

    for (int k0 = 0; k0 < 300; k0 += 16) {
        if (k0 + 16 <= 300) {
#pragma unroll
            for (int h = 0; h < 2; h++) {
                int r = a_row + h * 64;
                float4 v = *reinterpret_cast<const float4*>(&A[(m0 + r) * 300 + k0 + a_c4 * 4]);
                As[a_c4 * 4 + 0][r] = v.x;
                As[a_c4 * 4 + 1][r] = v.y;
                As[a_c4 * 4 + 2][r] = v.z;
                As[a_c4 * 4 + 3][r] = v.w;
            }
#pragma unroll
            for (int c = 0; c < 4; c++) {
                int n = n0 + b_nn + c;
                Bs[b_kk][b_nn + c] = (n < 300) ? Bm[(k0 + b_kk) * 300 + n] : 0.f;
            }
        } else {
#pragma unroll
            for (int h = 0; h < 2; h++) {
                int r = a_row + h * 64;
#pragma unroll
                for (int c = 0; c < 4; c++) {
                    int kk = k0 + a_c4 * 4 + c;
                    As[a_c4 * 4 + c][r] = (kk < 300) ? A[(m0 + r) * 300 + kk] : 0.f;
                }
            }
#pragma unroll
            for (int c = 0; c < 4; c++) {
                int kk = k0 + b_kk;
                int n = n0 + b_nn + c;
                Bs[b_kk][b_nn + c] = (kk < 300 && n < 300) ? Bm[kk * 300 + n] : 0.f;
            }
        }
        __syncthreads();
#pragma unroll
        for (int k = 0; k < 16; k++) {
            float4 a0 = *reinterpret_cast<const float4*>(&As[k][ty * 8]);
            float4 a1 = *reinterpret_cast<const float4*>(&As[k][ty * 8 + 4]);
            float4 bv = *reinterpret_cast<const float4*>(&Bs[k][tx * 4]);
            float ar[8] = {a0.x, a0.y, a0.z, a0.w, a1.x, a1.y, a1.z, a1.w};
            float br[4] = {bv.x, bv.y, bv.z, bv.w};
#pragma unroll
            for (int i = 0; i < 8; i++)
#pragma unroll
                for (int j = 0; j < 4; j++) acc[i][j] += ar[i] * br[j];
        }
        __syncthreads();
    }
#pragma unroll
    for (int i = 0; i < 8; i++) {
        int row = m0 + ty * 8 + i;
#pragma unroll
        for (int j = 0; j < 4; j++) {
            int col = n0 + tx * 4 + j;
            if (col < 300) Cm[row * 300 + col] = acc[i][j];
        }
    }
}

// ---------------- K4: shift-add combine -> ut(b,l,f), norms, zero att ----------------
__global__ void k_comb(const float* __restrict__ udb, const float* __restrict__ idb) {
    int side = blockIdx.y;
    int bl = blockIdx.x;
    int l = bl % Lsz;
    const float* bias = side ? idb : udb;
    const float* Cm = g_C[side];
    int f = threadIdx.x;  // 128 threads, active < 100
    float val = 0.f;
    if (f < Fsz) {
        val = bias[f] + Cm[bl * 300 + Fsz + f];
        if (l >= 1)       val += Cm[(bl - 1) * 300 + f];
        if (l < Lsz - 1)  val += Cm[(bl + 1) * 300 + 2 * Fsz + f];
        g_ut[side][bl * Fsz + f] = val;
    }
    float sq = val * val;
    sq = warpSum(sq);
    __shared__ float sh[4];
    int lane = threadIdx.x & 31, w = threadIdx.x >> 5;
    if (lane == 0) sh[w] = sq;
    __syncthreads();
    if (threadIdx.x == 0) {
        g_nrm[side][bl] = sh[0] + sh[1] + sh[2] + sh[3];
        g_att[side][bl] = 0.f;
    }
}

// ---------------- K5: tiled pairwise attention + row/col sum reduction ----------------
__global__ void k_att() {
    int b = blockIdx.z;
    int l0 = blockIdx.x * 64, m0 = blockIdx.y * 64;
    __shared__ float Us[50][65];
    __shared__ float Vs[50][65];
    __shared__ float rsum[64], csum[64];
    int tid = threadIdx.x;
    int tx = tid & 15, ty = tid >> 4;
    const float* U = g_ut[0] + (size_t)b * Lsz * Fsz;
    const float* V = g_ut[1] + (size_t)b * Lsz * Fsz;
    float acc[4][4];
#pragma unroll
    for (int i = 0; i < 4; i++)
#pragma unroll
        for (int j = 0; j < 4; j++) acc[i][j] = 0.f;

    for (int kc = 0; kc < Fsz; kc += 50) {
        __syncthreads();
        for (int i = tid; i < 64 * 50; i += 256) {
            int r = i / 50, c = i - r * 50;
            Us[c][r] = (l0 + r < Lsz) ? U[(l0 + r) * Fsz + kc + c] : 0.f;
            Vs[c][r] = (m0 + r < Lsz) ? V[(m0 + r) * Fsz + kc + c] : 0.f;
        }
        __syncthreads();
#pragma unroll 5
        for (int k = 0; k < 50; k++) {
            float ar[4], br[4];
#pragma unroll
            for (int i = 0; i < 4; i++) ar[i] = Us[k][ty * 4 + i];
#pragma unroll
            for (int j = 0; j < 4; j++) br[j] = Vs[k][tx * 4 + j];
#pragma unroll
            for (int i = 0; i < 4; i++)
#pragma unroll
                for (int j = 0; j < 4; j++) acc[i][j] += ar[i] * br[j];
        }
    }

    float nu[4], nv[4];
#pragma unroll
    for (int i = 0; i < 4; i++) {
        int l = l0 + ty * 4 + i;
        nu[i] = (l < Lsz) ? g_nrm[0][b * Lsz + l] : 0.f;
    }
#pragma unroll
    for (int j = 0; j < 4; j++) {
        int m = m0 + tx * 4 + j;
        nv[j] = (m < Lsz) ? g_nrm[1][b * Lsz + m] : 0.f;
    }
    float rs[4] = {0, 0, 0, 0}, cs[4] = {0, 0, 0, 0};
#pragma unroll
    for (int i = 0; i < 4; i++) {
        int l = l0 + ty * 4 + i;
#pragma unroll
        for (int j = 0; j < 4; j++) {
            int m = m0 + tx * 4 + j;
            if (l < Lsz && m < Lsz) {
                float sq = nu[i] + nv[j] - 2.f * acc[i][j];
                float a = 1.f / (1.f + sqrtf(fmaxf(sq, 1e-12f)));
                rs[i] += a;
                cs[j] += a;
            }
        }
    }
    if (tid < 64) { rsum[tid] = 0.f; csum[tid] = 0.f; }
    __syncthreads();
#pragma unroll
    for (int i = 0; i < 4; i++) atomicAdd(&rsum[ty * 4 + i], rs[i]);
#pragma unroll
    for (int j = 0; j < 4; j++) atomicAdd(&csum[tx * 4 + j], cs[j]);
    __syncthreads();
    if (tid < 64) {
        if (l0 + tid < Lsz) atomicAdd(&g_att[0][b * Lsz + l0 + tid], rsum[tid]);
        if (m0 + tid < Lsz) atomicAdd(&g_att[1][b * Lsz + m0 + tid], csum[tid]);
    }
}

// ---------------- K6: pooling (collapsed mean-of-conv) + FC head + id-emb gather ----------------
__global__ void k_head(const float* __restrict__ uacw, const float* __restrict__ uacb,
                       const float* __restrict__ iacw, const float* __restrict__ iacb,
                       const float* __restrict__ ufw,  const float* __restrict__ ufb,
                       const float* __restrict__ ifw,  const float* __restrict__ ifb,
                       const int* __restrict__ uids,   const int* __restrict__ iids,
                       const float* __restrict__ uide, const float* __restrict__ iide,
                       float* __restrict__ out) {
    int b = blockIdx.x;
    int side = blockIdx.y;
    const float* ut  = g_ut[side] + (size_t)b * Lsz * Fsz;
    const float* att = g_att[side] + b * Lsz;
    const float* acw = side ? iacw : uacw;
    const float* acb = side ? iacb : uacb;
    const float* fw  = side ? ifw : ufw;
    const float* fb  = side ? ifb : ufb;
    __shared__ float S[3][Fsz];
    __shared__ float am[Fsz];
    int t = threadIdx.x;

    if (t < Fsz) {
        float s0 = 0.f, s1 = 0.f, s2 = 0.f;
        float pm = 0.f;
        float pc = ut[t] * att[0];
        for (int l = 0; l < Lsz; l++) {
            float pn = (l + 1 < Lsz) ? ut[(l + 1) * Fsz + t] * att[l + 1] : 0.f;
            float s = pm + pc + pn;
            if (l <= Lsz - 3)           s0 += s;   // l in [0,497]
            if (l >= 1 && l <= Lsz - 2) s1 += s;   // l in [1,498]
            if (l >= 2)                 s2 += s;   // l in [2,499]
            pm = pc; pc = pn;
        }
        S[0][t] = s0; S[1][t] = s1; S[2][t] = s2;
    }
    __syncthreads();
    if (t < Fsz) {
        float a = 0.f;
#pragma unroll
        for (int k = 0; k < 3; k++)
            for (int g = 0; g < Fsz; g++)
                a += S[k][g] * acw[(t * 3 + k) * Fsz + g];
        am[t] = acb[t] + a * (1.f / (float)(Lsz - 2));
    }
    __syncthreads();
    if (t < IDs) {
        float o = fb[t];
        for (int f = 0; f < Fsz; f++) o += am[f] * fw[t * Fsz + f];
        o = fmaxf(o, 0.f);
        int base = side ? (Bsz * 2 * IDs) : 0;
        out[base + (b * 2 + 0) * IDs + t] = o;
    }
    if (t >= 64 && t < 64 + IDs) {
        int i = t - 64;
        if (side == 0) {
            out[(b * 2 + 1) * IDs + i] = iide[(size_t)iids[b] * IDs + i];
        } else {
            out[Bsz * 2 * IDs + (b * 2 + 1) * IDs + i] = uide[(size_t)uids[b] * IDs + i];
        }
    }
}

// ---------------- launch ----------------
extern "C" void kernel_launch(void* const* d_in, const int* in_sizes, int n_in,
                              void* d_out, int out_size) {
    const int*   uids = (const int*)d_in[0];
    const int*   iids = (const int*)d_in[1];
    const int*   udoc = (const int*)d_in[2];
    const int*   idoc = (const int*)d_in[3];
    const float* uemb = (const float*)d_in[4];
    const float* iemb = (const float*)d_in[5];
    const float* wcw  = (const float*)d_in[6];
    const float* wcb  = (const float*)d_in[7];
    const float* udcw = (const float*)d_in[8];
    const float* udcb = (const float*)d_in[9];
    const float* idcw = (const float*)d_in[10];
    const float* idcb = (const float*)d_in[11];
    const float* uacw = (const float*)d_in[12];
    const float* uacb = (const float*)d_in[13];
    const float* iacw = (const float*)d_in[14];
    const float* iacb = (const float*)d_in[15];
    const float* ufw  = (const float*)d_in[16];
    const float* ufb  = (const float*)d_in[17];
    const float* ifw  = (const float*)d_in[18];
    const float* ifb  = (const float*)d_in[19];
    const float* uide = (const float*)d_in[20];
    const float* iide = (const float*)d_in[21];
    float* out = (float*)d_out;

    k_prep<<<(300 * 300 + 255) / 256, 256>>>(udcw, idcw);
    dim3 gBL(BL, 2);
    k_gather<<<gBL, 128>>>(udoc, idoc, uemb, iemb, wcw);
    k_gate<<<gBL, 128>>>(wcb);
    k_gemm<<<dim3(250, 5, 2), 256>>>();
    k_comb<<<gBL, 128>>>(udcb, idcb);
    k_att<<<dim3(8, 8, Bsz), 256>>>();
    k_head<<<dim3(Bsz, 2), 128>>>(uacw, uacb, iacw, iacb, ufw, ufb, ifw, ifb,
                                  uids, iids, uide, iide, out);
}

// round 3
// speedup vs baseline: 1.1050x; 1.1050x over previous
#include <cuda_runtime.h>

#define Bsz 64
#define Lsz 500
#define Dsz 300
#define Fsz 100
#define IDs 32
#define BL  (Bsz*Lsz)   // 32000

// ---------------- scratch (static device globals; no allocation) ----------------
__device__ float g_eg[2][BL*Dsz];     // raw gathered embeddings (B*L, 300) per side
__device__ float g_dots[2][BL*3];     // word-gate partial dots
__device__ float g_gatev[2][BL];      // sigmoid gate scalar per (b,l)
__device__ float g_C[2][BL*300];      // GEMM out (B*L, 3F)
__device__ float g_ut[2][BL*Fsz];     // conv feature, layout (b,l,f)
__device__ float g_nrm[2][BL];        // per-(b,l) squared norms over F
__device__ float g_att[2][BL];        // attention row/col sums
__device__ float g_Wt[2][300*300];    // repacked doc-conv weights (d, k*F+f)

__device__ __forceinline__ float warpSum(float v) {
#pragma unroll
    for (int o = 16; o; o >>= 1) v += __shfl_down_sync(0xffffffffu, v, o);
    return v;
}

__device__ __forceinline__ unsigned f2tf32(float x) {
    unsigned r;
    asm("cvt.rna.tf32.f32 %0, %1;" : "=r"(r) : "f"(x));
    return r;
}

__device__ __forceinline__ void mma_tf32(float* c, const unsigned* a, const unsigned* b) {
    asm volatile(
        "mma.sync.aligned.m16n8k8.row.col.f32.tf32.tf32.f32 "
        "{%0,%1,%2,%3}, {%4,%5,%6,%7}, {%8,%9}, {%0,%1,%2,%3};\n"
        : "+f"(c[0]), "+f"(c[1]), "+f"(c[2]), "+f"(c[3])
        : "r"(a[0]), "r"(a[1]), "r"(a[2]), "r"(a[3]), "r"(b[0]), "r"(b[1]));
}

// ---------------- K0: repack doc-conv weights W[f,k,d] -> Wt[d, k*F+f] ----------------
__global__ void k_prep(const float* __restrict__ uw, const float* __restrict__ iw) {
    int idx = blockIdx.x * 256 + threadIdx.x;
    if (idx >= 300 * 300) return;
    int d = idx / 300, j = idx % 300;
    int k = j / Fsz, f = j % Fsz;
    g_Wt[0][idx] = uw[(f * 3 + k) * Dsz + d];
    g_Wt[1][idx] = iw[(f * 3 + k) * Dsz + d];
}

// ---------------- K1: gather embedding rows + 3 word-gate dots ----------------
__global__ void k_gather(const int* __restrict__ udoc, const int* __restrict__ idoc,
                         const float* __restrict__ uemb, const float* __restrict__ iemb,
                         const float* __restrict__ wc) {
    int side = blockIdx.y;
    int bl = blockIdx.x;
    const int* doc = side ? idoc : udoc;
    const float* emb = side ? iemb : uemb;
    int row = doc[bl];
    const float* e = emb + (size_t)row * Dsz;
    float* dst = g_eg[side] + (size_t)bl * Dsz;
    float p0 = 0.f, p1 = 0.f, p2 = 0.f;
    for (int d = threadIdx.x; d < Dsz; d += 128) {
        float v = e[d];
        dst[d] = v;
        p0 += v * wc[d];
        p1 += v * wc[Dsz + d];
        p2 += v * wc[2 * Dsz + d];
    }
    __shared__ float sh[3][4];
    p0 = warpSum(p0); p1 = warpSum(p1); p2 = warpSum(p2);
    int lane = threadIdx.x & 31, w = threadIdx.x >> 5;
    if (lane == 0) { sh[0][w] = p0; sh[1][w] = p1; sh[2][w] = p2; }
    __syncthreads();
    if (threadIdx.x == 0) {
        g_dots[side][bl * 3 + 0] = sh[0][0] + sh[0][1] + sh[0][2] + sh[0][3];
        g_dots[side][bl * 3 + 1] = sh[1][0] + sh[1][1] + sh[1][2] + sh[1][3];
        g_dots[side][bl * 3 + 2] = sh[2][0] + sh[2][1] + sh[2][2] + sh[2][3];
    }
}

// ---------------- K2: gate scalar only (fold multiply into GEMM A-load) ----------------
__global__ void k_gatev(const float* __restrict__ wcb) {
    int idx = blockIdx.x * 256 + threadIdx.x;
    if (idx >= 2 * BL) return;
    int side = idx / BL;
    int bl = idx - side * BL;
    int l = bl % Lsz;
    float g = g_dots[side][bl * 3 + 1] + wcb[0];
    if (l >= 1)       g += g_dots[side][(bl - 1) * 3 + 0];
    if (l <= Lsz - 2) g += g_dots[side][(bl + 1) * 3 + 2];
    g_gatev[side][bl] = 1.f / (1.f + __expf(-g));
}

// ---------------- K3: tensor-core GEMM (32000 x 300) @ (300 x 300), 3xTF32 ----------------
// BM=128, BN=64, BK=16, 256 threads (8 warps as 4x2), warp tile 32x32.
__global__ __launch_bounds__(256, 2) void k_gemm_tc() {
    const int side = blockIdx.z;
    const float* __restrict__ A  = g_eg[side];
    const float* __restrict__ Bm = g_Wt[side];
    const float* __restrict__ gv = g_gatev[side];
    float* __restrict__ Cm = g_C[side];

    __shared__ float Ah[16][136], Al[16][136];   // [k][m], stride 136 (conflict-free frags)
    __shared__ float Bh[16][72],  Bl[16][72];    // [k][n], stride 72
    __shared__ float gs[128];

    const int tid = threadIdx.x;
    const int lane = tid & 31, wid = tid >> 5;
    const int wm = wid >> 1, wn = wid & 1;       // warp grid 4 x 2
    const int m0 = blockIdx.x * 128;
    const int n0 = blockIdx.y * 64;

    if (tid < 128) gs[tid] = gv[m0 + tid];

    float acc[2][4][4];
#pragma unroll
    for (int i = 0; i < 2; i++)
#pragma unroll
        for (int j = 0; j < 4; j++)
#pragma unroll
            for (int q = 0; q < 4; q++) acc[i][j][q] = 0.f;

    const int arow  = tid >> 1;        // 0..127
    const int ahalf = tid & 1;         // 0..1 -> k offset 0/8
    const int bk    = tid >> 4;        // 0..15
    const int bn4   = (tid & 15) * 4;  // 0..60

    __syncthreads();

    for (int k0 = 0; k0 < 300; k0 += 16) {
        // --- load + gate + tf32-split A tile ---
        float av[8];
        const float gate = gs[arow];
        const size_t abase = (size_t)(m0 + arow) * 300 + k0 + ahalf * 8;
        if (k0 + 16 <= 300) {
            float4 v0 = *reinterpret_cast<const float4*>(&A[abase]);
            float4 v1 = *reinterpret_cast<const float4*>(&A[abase + 4]);
            av[0] = v0.x; av[1] = v0.y; av[2] = v0.z; av[3] = v0.w;
            av[4] = v1.x; av[5] = v1.y; av[6] = v1.z; av[7] = v1.w;
        } else {
#pragma unroll
            for (int j = 0; j < 8; j++) {
                int kk = k0 + ahalf * 8 + j;
                av[j] = (kk < 300) ? A[(size_t)(m0 + arow) * 300 + kk] : 0.f;
            }
        }
#pragma unroll
        for (int j = 0; j < 8; j++) {
            float x = av[j] * gate;
            unsigned hb = f2tf32(x);
            float hf = __uint_as_float(hb);
            unsigned lb = f2tf32(x - hf);
            Ah[ahalf * 8 + j][arow] = hf;
            Al[ahalf * 8 + j][arow] = __uint_as_float(lb);
        }
        // --- load + tf32-split B tile ---
        {
            int kk = k0 + bk;
#pragma unroll
            for (int c = 0; c < 4; c++) {
                int n = n0 + bn4 + c;
                float x = (n < 300 && kk < 300) ? Bm[kk * 300 + n] : 0.f;
                unsigned hb = f2tf32(x);
                float hf = __uint_as_float(hb);
                unsigned lb = f2tf32(x - hf);
                Bh[bk][bn4 + c] = hf;
                Bl[bk][bn4 + c] = __uint_as_float(lb);
            }
        }
        __syncthreads();

#pragma unroll
        for (int ks = 0; ks < 2; ks++) {
            const int kb = ks * 8;
            unsigned a_hi[2][4], a_lo[2][4], b_hi[4][2], b_lo[4][2];
#pragma unroll
            for (int mt = 0; mt < 2; mt++) {
                int r = wm * 32 + mt * 16 + (lane >> 2);
                int c = kb + (lane & 3);
                a_hi[mt][0] = __float_as_uint(Ah[c][r]);
                a_hi[mt][1] = __float_as_uint(Ah[c][r + 8]);
                a_hi[mt][2] = __float_as_uint(Ah[c + 4][r]);
                a_hi[mt][3] = __float_as_uint(Ah[c + 4][r + 8]);
                a_lo[mt][0] = __float_as_uint(Al[c][r]);
                a_lo[mt][1] = __float_as_uint(Al[c][r + 8]);
                a_lo[mt][2] = __float_as_uint(Al[c + 4][r]);
                a_lo[mt][3] = __float_as_uint(Al[c + 4][r + 8]);
            }
#pragma unroll
            for (int nt = 0; nt < 4; nt++) {
                int nn = wn * 32 + nt * 8 + (lane >> 2);
                int ck = kb + (lane & 3);
                b_hi[nt][0] = __float_as_uint(Bh[ck][nn]);
                b_hi[nt][1] = __float_as_uint(Bh[ck + 4][nn]);
                b_lo[nt][0] = __float_as_uint(Bl[ck][nn]);
                b_lo[nt][1] = __float_as_uint(Bl[ck + 4][nn]);
            }
#pragma unroll
            for (int mt = 0; mt < 2; mt++)
#pragma unroll
                for (int nt = 0; nt < 4; nt++) {
                    mma_tf32(acc[mt][nt], a_hi[mt], b_hi[nt]);
                    mma_tf32(acc[mt][nt], a_hi[mt], b_lo[nt]);
                    mma_tf32(acc[mt][nt], a_lo[mt], b_hi[nt]);
                }
        }
        __syncthreads();
    }

    // --- epilogue ---
#pragma unroll
    for (int mt = 0; mt < 2; mt++) {
        int r = m0 + wm * 32 + mt * 16 + (lane >> 2);
#pragma unroll
        for (int nt = 0; nt < 4; nt++) {
            int c = n0 + wn * 32 + nt * 8 + 2 * (lane & 3);
            if (c < 300) {
                Cm[(size_t)r * 300 + c] = acc[mt][nt][0];
                if (c + 1 < 300) Cm[(size_t)r * 300 + c + 1] = acc[mt][nt][1];
                Cm[(size_t)(r + 8) * 300 + c] = acc[mt][nt][2];
                if (c + 1 < 300) Cm[(size_t)(r + 8) * 300 + c + 1] = acc[mt][nt][3];
            }
        }
    }
}

// ---------------- K4: shift-add combine -> ut(b,l,f), norms, zero att ----------------
__global__ void k_comb(const float* __restrict__ udb, const float* __restrict__ idb) {
    int side = blockIdx.y;
    int bl = blockIdx.x;
    int l = bl % Lsz;
    const float* bias = side ? idb : udb;
    const float* Cm = g_C[side];
    int f = threadIdx.x;  // 128 threads, active < 100
    float val = 0.f;
    if (f < Fsz) {
        val = bias[f] + Cm[bl * 300 + Fsz + f];
        if (l >= 1)       val += Cm[(bl - 1) * 300 + f];
        if (l < Lsz - 1)  val += Cm[(bl + 1) * 300 + 2 * Fsz + f];
        g_ut[side][bl * Fsz + f] = val;
    }
    float sq = val * val;
    sq = warpSum(sq);
    __shared__ float sh[4];
    int lane = threadIdx.x & 31, w = threadIdx.x >> 5;
    if (lane == 0) sh[w] = sq;
    __syncthreads();
    if (threadIdx.x == 0) {
        g_nrm[side][bl] = sh[0] + sh[1] + sh[2] + sh[3];
        g_att[side][bl] = 0.f;
    }
}

// ---------------- K5: tiled pairwise attention + row/col sum reduction ----------------
__global__ void k_att() {
    int b = blockIdx.z;
    int l0 = blockIdx.x * 64, m0 = blockIdx.y * 64;
    __shared__ float Us[50][65];
    __shared__ float Vs[50][65];
    __shared__ float rsum[64], csum[64];
    int tid = threadIdx.x;
    int tx = tid & 15, ty = tid >> 4;
    const float* U = g_ut[0] + (size_t)b * Lsz * Fsz;
    const float* V = g_ut[1] + (size_t)b * Lsz * Fsz;
    float acc[4][4];
#pragma unroll
    for (int i = 0; i < 4; i++)
#pragma unroll
        for (int j = 0; j < 4; j++) acc[i][j] = 0.f;

    for (int kc = 0; kc < Fsz; kc += 50) {
        __syncthreads();
        for (int i = tid; i < 64 * 50; i += 256) {
            int r = i / 50, c = i - r * 50;
            Us[c][r] = (l0 + r < Lsz) ? U[(l0 + r) * Fsz + kc + c] : 0.f;
            Vs[c][r] = (m0 + r < Lsz) ? V[(m0 + r) * Fsz + kc + c] : 0.f;
        }
        __syncthreads();
#pragma unroll 5
        for (int k = 0; k < 50; k++) {
            float ar[4], br[4];
#pragma unroll
            for (int i = 0; i < 4; i++) ar[i] = Us[k][ty * 4 + i];
#pragma unroll
            for (int j = 0; j < 4; j++) br[j] = Vs[k][tx * 4 + j];
#pragma unroll
            for (int i = 0; i < 4; i++)
#pragma unroll
                for (int j = 0; j < 4; j++) acc[i][j] += ar[i] * br[j];
        }
    }

    float nu[4], nv[4];
#pragma unroll
    for (int i = 0; i < 4; i++) {
        int l = l0 + ty * 4 + i;
        nu[i] = (l < Lsz) ? g_nrm[0][b * Lsz + l] : 0.f;
    }
#pragma unroll
    for (int j = 0; j < 4; j++) {
        int m = m0 + tx * 4 + j;
        nv[j] = (m < Lsz) ? g_nrm[1][b * Lsz + m] : 0.f;
    }
    float rs[4] = {0, 0, 0, 0}, cs[4] = {0, 0, 0, 0};
#pragma unroll
    for (int i = 0; i < 4; i++) {
        int l = l0 + ty * 4 + i;
#pragma unroll
        for (int j = 0; j < 4; j++) {
            int m = m0 + tx * 4 + j;
            if (l < Lsz && m < Lsz) {
                float sq = nu[i] + nv[j] - 2.f * acc[i][j];
                float a = 1.f / (1.f + sqrtf(fmaxf(sq, 1e-12f)));
                rs[i] += a;
                cs[j] += a;
            }
        }
    }
    if (tid < 64) { rsum[tid] = 0.f; csum[tid] = 0.f; }
    __syncthreads();
#pragma unroll
    for (int i = 0; i < 4; i++) atomicAdd(&rsum[ty * 4 + i], rs[i]);
#pragma unroll
    for (int j = 0; j < 4; j++) atomicAdd(&csum[tx * 4 + j], cs[j]);
    __syncthreads();
    if (tid < 64) {
        if (l0 + tid < Lsz) atomicAdd(&g_att[0][b * Lsz + l0 + tid], rsum[tid]);
        if (m0 + tid < Lsz) atomicAdd(&g_att[1][b * Lsz + m0 + tid], csum[tid]);
    }
}

// ---------------- K6: pooling (collapsed mean-of-conv) + FC head + id-emb gather ----------------
__global__ void k_head(const float* __restrict__ uacw, const float* __restrict__ uacb,
                       const float* __restrict__ iacw, const float* __restrict__ iacb,
                       const float* __restrict__ ufw,  const float* __restrict__ ufb,
                       const float* __restrict__ ifw,  const float* __restrict__ ifb,
                       const int* __restrict__ uids,   const int* __restrict__ iids,
                       const float* __restrict__ uide, const float* __restrict__ iide,
                       float* __restrict__ out) {
    int b = blockIdx.x;
    int side = blockIdx.y;
    const float* ut  = g_ut[side] + (size_t)b * Lsz * Fsz;
    const float* att = g_att[side] + b * Lsz;
    const float* acw = side ? iacw : uacw;
    const float* acb = side ? iacb : uacb;
    const float* fw  = side ? ifw : ufw;
    const float* fb  = side ? ifb : ufb;
    __shared__ float S[3][Fsz];
    __shared__ float am[Fsz];
    int t = threadIdx.x;

    if (t < Fsz) {
        float s0 = 0.f, s1 = 0.f, s2 = 0.f;
        float pm = 0.f;
        float pc = ut[t] * att[0];
        for (int l = 0; l < Lsz; l++) {
            float pn = (l + 1 < Lsz) ? ut[(l + 1) * Fsz + t] * att[l + 1] : 0.f;
            float s = pm + pc + pn;
            if (l <= Lsz - 3)           s0 += s;
            if (l >= 1 && l <= Lsz - 2) s1 += s;
            if (l >= 2)                 s2 += s;
            pm = pc; pc = pn;
        }
        S[0][t] = s0; S[1][t] = s1; S[2][t] = s2;
    }
    __syncthreads();
    if (t < Fsz) {
        float a = 0.f;
#pragma unroll
        for (int k = 0; k < 3; k++)
            for (int g = 0; g < Fsz; g++)
                a += S[k][g] * acw[(t * 3 + k) * Fsz + g];
        am[t] = acb[t] + a * (1.f / (float)(Lsz - 2));
    }
    __syncthreads();
    if (t < IDs) {
        float o = fb[t];
        for (int f = 0; f < Fsz; f++) o += am[f] * fw[t * Fsz + f];
        o = fmaxf(o, 0.f);
        int base = side ? (Bsz * 2 * IDs) : 0;
        out[base + (b * 2 + 0) * IDs + t] = o;
    }
    if (t >= 64 && t < 64 + IDs) {
        int i = t - 64;
        if (side == 0) {
            out[(b * 2 + 1) * IDs + i] = iide[(size_t)iids[b] * IDs + i];
        } else {
            out[Bsz * 2 * IDs + (b * 2 + 1) * IDs + i] = uide[(size_t)uids[b] * IDs + i];
        }
    }
}

// ---------------- launch ----------------
extern "C" void kernel_launch(void* const* d_in, const int* in_sizes, int n_in,
                              void* d_out, int out_size) {
    const int*   uids = (const int*)d_in[0];
    const int*   iids = (const int*)d_in[1];
    const int*   udoc = (const int*)d_in[2];
    const int*   idoc = (const int*)d_in[3];
    const float* uemb = (const float*)d_in[4];
    const float* iemb = (const float*)d_in[5];
    const float* wcw  = (const float*)d_in[6];
    const float* wcb  = (const float*)d_in[7];
    const float* udcw = (const float*)d_in[8];
    const float* udcb = (const float*)d_in[9];
    const float* idcw = (const float*)d_in[10];
    const float* idcb = (const float*)d_in[11];
    const float* uacw = (const float*)d_in[12];
    const float* uacb = (const float*)d_in[13];
    const float* iacw = (const float*)d_in[14];
    const float* iacb = (const float*)d_in[15];
    const float* ufw  = (const float*)d_in[16];
    const float* ufb  = (const float*)d_in[17];
    const float* ifw  = (const float*)d_in[18];
    const float* ifb  = (const float*)d_in[19];
    const float* uide = (const float*)d_in[20];
    const float* iide = (const float*)d_in[21];
    float* out = (float*)d_out;

    k_prep<<<(300 * 300 + 255) / 256, 256>>>(udcw, idcw);
    dim3 gBL(BL, 2);
    k_gather<<<gBL, 128>>>(udoc, idoc, uemb, iemb, wcw);
    k_gatev<<<(2 * BL + 255) / 256, 256>>>(wcb);
    k_gemm_tc<<<dim3(250, 5, 2), 256>>>();
    k_comb<<<gBL, 128>>>(udcb, idcb);
    k_att<<<dim3(8, 8, Bsz), 256>>>();
    k_head<<<dim3(Bsz, 2), 128>>>(uacw, uacb, iacw, iacb, ufw, ufb, ifw, ifb,
                                  uids, iids, uide, iide, out);
}

// round 4
// speedup vs baseline: 1.4592x; 1.3206x over previous
#include <cuda_runtime.h>
#include <cuda_bf16.h>

#define Bsz 64
#define Lsz 500
#define Dsz 300
#define Fsz 100
#define IDs 32
#define BL  (Bsz*Lsz)   // 32000
#define KP  320         // padded K (and padded N) for the doc GEMM
#define NK  20          // KP / 16 k-iterations

// ---------------- scratch (static device globals; no allocation) ----------------
__device__ __nv_bfloat16 g_Ah[2][BL*KP];    // A hi split (gathered emb, ungated)
__device__ __nv_bfloat16 g_Al[2][BL*KP];    // A lo split
__device__ __nv_bfloat16 g_Wh[2][KP*KP];    // B hi split, layout [n][k]
__device__ __nv_bfloat16 g_Wl[2][KP*KP];    // B lo split
__device__ float g_dots[2][BL*3];           // word-gate partial dots
__device__ float g_gatev[2][BL];            // sigmoid gate scalar per (b,l)
__device__ float g_C[2][BL*300];            // GEMM out (B*L, 3F), ungated
__device__ float g_ut[2][BL*Fsz];           // conv feature, layout (b,l,f)
__device__ float g_nrm[2][BL];              // per-(b,l) squared norms over F
__device__ float g_att[2][BL];              // attention row/col sums

__device__ __forceinline__ float warpSum(float v) {
#pragma unroll
    for (int o = 16; o; o >>= 1) v += __shfl_down_sync(0xffffffffu, v, o);
    return v;
}

__device__ __forceinline__ unsigned pack_bf(float x0, float x1,
                                            float& r0, float& r1) {
    __nv_bfloat16 h0 = __float2bfloat16(x0);
    __nv_bfloat16 h1 = __float2bfloat16(x1);
    r0 = x0 - __bfloat162float(h0);
    r1 = x1 - __bfloat162float(h1);
    return (unsigned)__bfloat16_as_ushort(h0) |
           ((unsigned)__bfloat16_as_ushort(h1) << 16);
}

__device__ __forceinline__ void ldsm4(unsigned& r0, unsigned& r1,
                                      unsigned& r2, unsigned& r3, unsigned addr) {
    asm volatile("ldmatrix.sync.aligned.m8n8.x4.shared.b16 {%0,%1,%2,%3}, [%4];"
                 : "=r"(r0), "=r"(r1), "=r"(r2), "=r"(r3) : "r"(addr));
}

__device__ __forceinline__ void mma_bf16(float* c, const unsigned* a, const unsigned* b) {
    asm volatile(
        "mma.sync.aligned.m16n8k16.row.col.f32.bf16.bf16.f32 "
        "{%0,%1,%2,%3}, {%4,%5,%6,%7}, {%8,%9}, {%0,%1,%2,%3};\n"
        : "+f"(c[0]), "+f"(c[1]), "+f"(c[2]), "+f"(c[3])
        : "r"(a[0]), "r"(a[1]), "r"(a[2]), "r"(a[3]), "r"(b[0]), "r"(b[1]));
}

__device__ __forceinline__ void cp16(unsigned sdst, const void* gsrc) {
    asm volatile("cp.async.cg.shared.global [%0], [%1], 16;"
                 :: "r"(sdst), "l"(gsrc));
}
__device__ __forceinline__ void cp_commit() {
    asm volatile("cp.async.commit_group;");
}
template <int N>
__device__ __forceinline__ void cp_wait() {
    asm volatile("cp.async.wait_group %0;" :: "n"(N));
}

// ---------------- K0: repack + bf16-split doc-conv weights -> [n][k] padded ----------------
__global__ void k_prep(const float* __restrict__ uw, const float* __restrict__ iw) {
    int idx = blockIdx.x * 256 + threadIdx.x;
    if (idx >= 2 * KP * KP) return;
    int side = idx / (KP * KP);
    int r = idx - side * KP * KP;
    int n = r / KP, k = r % KP;
    float x = 0.f;
    if (n < 300 && k < 300) {
        int f = n % Fsz, ks = n / Fsz;
        const float* w = side ? iw : uw;
        x = w[(f * 3 + ks) * Dsz + k];
    }
    __nv_bfloat16 h = __float2bfloat16(x);
    float lo = x - __bfloat162float(h);
    g_Wh[side][n * KP + k] = h;
    g_Wl[side][n * KP + k] = __float2bfloat16(lo);
}

// ---------------- K1: gather + word-gate dots + bf16 hi/lo split (ungated) ----------------
__global__ void k_gather(const int* __restrict__ udoc, const int* __restrict__ idoc,
                         const float* __restrict__ uemb, const float* __restrict__ iemb,
                         const float* __restrict__ wc) {
    int side = blockIdx.y;
    int bl = blockIdx.x;
    const int* doc = side ? idoc : udoc;
    const float* emb = side ? iemb : uemb;
    int row = doc[bl];
    const float* e = emb + (size_t)row * Dsz;
    unsigned* ah = reinterpret_cast<unsigned*>(&g_Ah[side][(size_t)bl * KP]);
    unsigned* al = reinterpret_cast<unsigned*>(&g_Al[side][(size_t)bl * KP]);
    float p0 = 0.f, p1 = 0.f, p2 = 0.f;
    for (int p = threadIdx.x; p < KP / 2; p += 128) {
        int d = 2 * p;
        float x0 = 0.f, x1 = 0.f;
        if (d < 300) {
            float2 v = *reinterpret_cast<const float2*>(&e[d]);
            x0 = v.x; x1 = v.y;
            p0 += x0 * wc[d]       + x1 * wc[d + 1];
            p1 += x0 * wc[300 + d] + x1 * wc[301 + d];
            p2 += x0 * wc[600 + d] + x1 * wc[601 + d];
        }
        float l0, l1;
        unsigned hp = pack_bf(x0, x1, l0, l1);
        __nv_bfloat16 lb0 = __float2bfloat16(l0);
        __nv_bfloat16 lb1 = __float2bfloat16(l1);
        ah[p] = hp;
        al[p] = (unsigned)__bfloat16_as_ushort(lb0) |
                ((unsigned)__bfloat16_as_ushort(lb1) << 16);
    }
    __shared__ float sh[3][4];
    p0 = warpSum(p0); p1 = warpSum(p1); p2 = warpSum(p2);
    int lane = threadIdx.x & 31, w = threadIdx.x >> 5;
    if (lane == 0) { sh[0][w] = p0; sh[1][w] = p1; sh[2][w] = p2; }
    __syncthreads();
    if (threadIdx.x == 0) {
        g_dots[side][bl * 3 + 0] = sh[0][0] + sh[0][1] + sh[0][2] + sh[0][3];
        g_dots[side][bl * 3 + 1] = sh[1][0] + sh[1][1] + sh[1][2] + sh[1][3];
        g_dots[side][bl * 3 + 2] = sh[2][0] + sh[2][1] + sh[2][2] + sh[2][3];
    }
}

// ---------------- K2: gate scalar (applied later, in k_comb) ----------------
__global__ void k_gatev(const float* __restrict__ wcb) {
    int idx = blockIdx.x * 256 + threadIdx.x;
    if (idx >= 2 * BL) return;
    int side = idx / BL;
    int bl = idx - side * BL;
    int l = bl % Lsz;
    float g = g_dots[side][bl * 3 + 1] + wcb[0];
    if (l >= 1)       g += g_dots[side][(bl - 1) * 3 + 0];
    if (l <= Lsz - 2) g += g_dots[side][(bl + 1) * 3 + 2];
    g_gatev[side][bl] = 1.f / (1.f + __expf(-g));
}

// ---------------- K3: bf16 tensor-core GEMM (32000x320) @ (320x320), 3-term split ----
// BM=128, BN=64, BK=16, 256 threads (8 warps 4x2), warp tile 32x32.
// cp.async double-buffered; ldmatrix fragments; conflict-free 48B row stride.
__global__ __launch_bounds__(256, 2) void k_gemm_bf16() {
    const int side = blockIdx.z;
    float* __restrict__ Cm = g_C[side];

    // stage layout (bytes): Ah 0..6143 (128 rows x 48B), Al 6144.., Bh 12288.. (64x48), Bl 15360..
    __shared__ __align__(16) unsigned char smbuf[2][18432];

    const int tid = threadIdx.x;
    const int lane = tid & 31, wid = tid >> 5;
    const int wm = wid >> 1, wn = wid & 1;
    const int m0 = blockIdx.x * 128;
    const int n0 = blockIdx.y * 64;

    // cp.async mapping: thread does 3 x 16B chunks per stage
    const int arow = tid >> 1, ahalf = tid & 1;
    const char* gA_h = (const char*)&g_Ah[side][((size_t)(m0 + arow)) * KP + ahalf * 8];
    const char* gA_l = (const char*)&g_Al[side][((size_t)(m0 + arow)) * KP + ahalf * 8];
    const unsigned sA_h = (unsigned)__cvta_generic_to_shared(&smbuf[0][0]) + arow * 48 + ahalf * 16;
    const unsigned sA_l = sA_h + 6144;
    const int brow = (tid & 127) >> 1;
    const __nv_bfloat16* gBarr = (tid < 128) ? g_Wh[side] : g_Wl[side];
    const char* gB = (const char*)&gBarr[((size_t)(n0 + brow)) * KP + ahalf * 8];
    const unsigned sB = (unsigned)__cvta_generic_to_shared(&smbuf[0][0]) +
                        ((tid < 128) ? 12288u : 15360u) + brow * 48 + ahalf * 16;

    float acc[2][4][4];
#pragma unroll
    for (int i = 0; i < 2; i++)
#pragma unroll
        for (int j = 0; j < 4; j++)
#pragma unroll
            for (int q = 0; q < 4; q++) acc[i][j][q] = 0.f;

    // prologue: stages 0 and 1
#pragma unroll
    for (int s = 0; s < 2; s++) {
        cp16(sA_h + s * 18432, gA_h + s * 32);
        cp16(sA_l + s * 18432, gA_l + s * 32);
        cp16(sB   + s * 18432, gB   + s * 32);
        cp_commit();
    }

    // fragment addresses (per-stage base added in loop)
    const int l4 = lane & 7, g4 = lane >> 3;
    const unsigned smem0 = (unsigned)__cvta_generic_to_shared(&smbuf[0][0]);
    // A: matrices ordered m0-7/k0-7, m8-15/k0-7, m0-7/k8-15, m8-15/k8-15
    unsigned aoff[2];
#pragma unroll
    for (int mt = 0; mt < 2; mt++) {
        int rowm = wm * 32 + mt * 16 + (g4 & 1) * 8 + l4;
        int koff = (g4 >> 1) * 8;
        aoff[mt] = smem0 + (rowm * 24 + koff) * 2;
    }
    // B: matrices ordered n0-7/k0-7, n0-7/k8-15, n8-15/k0-7, n8-15/k8-15
    unsigned boff[2];
#pragma unroll
    for (int ntp = 0; ntp < 2; ntp++) {
        int rown = wn * 32 + ntp * 16 + (g4 >> 1) * 8 + l4;
        int koff = (g4 & 1) * 8;
        boff[ntp] = smem0 + 12288 + (rown * 24 + koff) * 2;
    }

    for (int it = 0; it < NK; it++) {
        const unsigned sbase = (it & 1) * 18432u;
        cp_wait<1>();
        __syncthreads();

        unsigned a_h[2][4], a_l[2][4], b_h[2][4], b_l[2][4];
#pragma unroll
        for (int mt = 0; mt < 2; mt++) {
            ldsm4(a_h[mt][0], a_h[mt][1], a_h[mt][2], a_h[mt][3], aoff[mt] + sbase);
            ldsm4(a_l[mt][0], a_l[mt][1], a_l[mt][2], a_l[mt][3], aoff[mt] + sbase + 6144);
        }
#pragma unroll
        for (int ntp = 0; ntp < 2; ntp++) {
            ldsm4(b_h[ntp][0], b_h[ntp][1], b_h[ntp][2], b_h[ntp][3], boff[ntp] + sbase);
            ldsm4(b_l[ntp][0], b_l[ntp][1], b_l[ntp][2], b_l[ntp][3], boff[ntp] + sbase + 3072);
        }
#pragma unroll
        for (int mt = 0; mt < 2; mt++)
#pragma unroll
            for (int nt = 0; nt < 4; nt++) {
                const int bi = nt >> 1, bo = (nt & 1) * 2;
                mma_bf16(acc[mt][nt], a_h[mt], &b_h[bi][bo]);
                mma_bf16(acc[mt][nt], a_h[mt], &b_l[bi][bo]);
                mma_bf16(acc[mt][nt], a_l[mt], &b_h[bi][bo]);
            }
        __syncthreads();
        if (it + 2 < NK) {
            cp16(sA_h + sbase, gA_h + (it + 2) * 32);
            cp16(sA_l + sbase, gA_l + (it + 2) * 32);
            cp16(sB   + sbase, gB   + (it + 2) * 32);
        }
        cp_commit();
    }

    // epilogue
#pragma unroll
    for (int mt = 0; mt < 2; mt++) {
        int r = m0 + wm * 32 + mt * 16 + (lane >> 2);
#pragma unroll
        for (int nt = 0; nt < 4; nt++) {
            int c = n0 + wn * 32 + nt * 8 + 2 * (lane & 3);
            if (c < 300) {
                Cm[(size_t)r * 300 + c] = acc[mt][nt][0];
                if (c + 1 < 300) Cm[(size_t)r * 300 + c + 1] = acc[mt][nt][1];
                Cm[(size_t)(r + 8) * 300 + c] = acc[mt][nt][2];
                if (c + 1 < 300) Cm[(size_t)(r + 8) * 300 + c + 1] = acc[mt][nt][3];
            }
        }
    }
}

// ---------------- K4: gated shift-add combine -> ut(b,l,f), norms, zero att ----------------
__global__ void k_comb(const float* __restrict__ udb, const float* __restrict__ idb) {
    int side = blockIdx.y;
    int bl = blockIdx.x;
    int l = bl % Lsz;
    const float* bias = side ? idb : udb;
    const float* Cm = g_C[side];
    const float* gv = g_gatev[side];
    int f = threadIdx.x;
    float val = 0.f;
    if (f < Fsz) {
        val = bias[f] + gv[bl] * Cm[bl * 300 + Fsz + f];
        if (l >= 1)       val += gv[bl - 1] * Cm[(bl - 1) * 300 + f];
        if (l < Lsz - 1)  val += gv[bl + 1] * Cm[(bl + 1) * 300 + 2 * Fsz + f];
        g_ut[side][bl * Fsz + f] = val;
    }
    float sq = val * val;
    sq = warpSum(sq);
    __shared__ float sh[4];
    int lane = threadIdx.x & 31, w = threadIdx.x >> 5;
    if (lane == 0) sh[w] = sq;
    __syncthreads();
    if (threadIdx.x == 0) {
        g_nrm[side][bl] = sh[0] + sh[1] + sh[2] + sh[3];
        g_att[side][bl] = 0.f;
    }
}

// ---------------- K5: tiled pairwise attention + row/col sum reduction ----------------
__global__ void k_att() {
    int b = blockIdx.z;
    int l0 = blockIdx.x * 64, m0 = blockIdx.y * 64;
    __shared__ float Us[50][65];
    __shared__ float Vs[50][65];
    __shared__ float rsum[64], csum[64];
    int tid = threadIdx.x;
    int tx = tid & 15, ty = tid >> 4;
    const float* U = g_ut[0] + (size_t)b * Lsz * Fsz;
    const float* V = g_ut[1] + (size_t)b * Lsz * Fsz;
    float acc[4][4];
#pragma unroll
    for (int i = 0; i < 4; i++)
#pragma unroll
        for (int j = 0; j < 4; j++) acc[i][j] = 0.f;

    for (int kc = 0; kc < Fsz; kc += 50) {
        __syncthreads();
        for (int i = tid; i < 64 * 50; i += 256) {
            int r = i / 50, c = i - r * 50;
            Us[c][r] = (l0 + r < Lsz) ? U[(l0 + r) * Fsz + kc + c] : 0.f;
            Vs[c][r] = (m0 + r < Lsz) ? V[(m0 + r) * Fsz + kc + c] : 0.f;
        }
        __syncthreads();
#pragma unroll 5
        for (int k = 0; k < 50; k++) {
            float ar[4], br[4];
#pragma unroll
            for (int i = 0; i < 4; i++) ar[i] = Us[k][ty * 4 + i];
#pragma unroll
            for (int j = 0; j < 4; j++) br[j] = Vs[k][tx * 4 + j];
#pragma unroll
            for (int i = 0; i < 4; i++)
#pragma unroll
                for (int j = 0; j < 4; j++) acc[i][j] += ar[i] * br[j];
        }
    }

    float nu[4], nv[4];
#pragma unroll
    for (int i = 0; i < 4; i++) {
        int l = l0 + ty * 4 + i;
        nu[i] = (l < Lsz) ? g_nrm[0][b * Lsz + l] : 0.f;
    }
#pragma unroll
    for (int j = 0; j < 4; j++) {
        int m = m0 + tx * 4 + j;
        nv[j] = (m < Lsz) ? g_nrm[1][b * Lsz + m] : 0.f;
    }
    float rs[4] = {0, 0, 0, 0}, cs[4] = {0, 0, 0, 0};
#pragma unroll
    for (int i = 0; i < 4; i++) {
        int l = l0 + ty * 4 + i;
#pragma unroll
        for (int j = 0; j < 4; j++) {
            int m = m0 + tx * 4 + j;
            if (l < Lsz && m < Lsz) {
                float sq = nu[i] + nv[j] - 2.f * acc[i][j];
                float a = 1.f / (1.f + sqrtf(fmaxf(sq, 1e-12f)));
                rs[i] += a;
                cs[j] += a;
            }
        }
    }
    if (tid < 64) { rsum[tid] = 0.f; csum[tid] = 0.f; }
    __syncthreads();
#pragma unroll
    for (int i = 0; i < 4; i++) atomicAdd(&rsum[ty * 4 + i], rs[i]);
#pragma unroll
    for (int j = 0; j < 4; j++) atomicAdd(&csum[tx * 4 + j], cs[j]);
    __syncthreads();
    if (tid < 64) {
        if (l0 + tid < Lsz) atomicAdd(&g_att[0][b * Lsz + l0 + tid], rsum[tid]);
        if (m0 + tid < Lsz) atomicAdd(&g_att[1][b * Lsz + m0 + tid], csum[tid]);
    }
}

// ---------------- K6: pooling (collapsed mean-of-conv) + FC head + id-emb gather ----------------
__global__ void k_head(const float* __restrict__ uacw, const float* __restrict__ uacb,
                       const float* __restrict__ iacw, const float* __restrict__ iacb,
                       const float* __restrict__ ufw,  const float* __restrict__ ufb,
                       const float* __restrict__ ifw,  const float* __restrict__ ifb,
                       const int* __restrict__ uids,   const int* __restrict__ iids,
                       const float* __restrict__ uide, const float* __restrict__ iide,
                       float* __restrict__ out) {
    int b = blockIdx.x;
    int side = blockIdx.y;
    const float* ut  = g_ut[side] + (size_t)b * Lsz * Fsz;
    const float* att = g_att[side] + b * Lsz;
    const float* acw = side ? iacw : uacw;
    const float* acb = side ? iacb : uacb;
    const float* fw  = side ? ifw : ufw;
    const float* fb  = side ? ifb : ufb;
    __shared__ float S[3][Fsz];
    __shared__ float am[Fsz];
    int t = threadIdx.x;

    if (t < Fsz) {
        float s0 = 0.f, s1 = 0.f, s2 = 0.f;
        float pm = 0.f;
        float pc = ut[t] * att[0];
        for (int l = 0; l < Lsz; l++) {
            float pn = (l + 1 < Lsz) ? ut[(l + 1) * Fsz + t] * att[l + 1] : 0.f;
            float s = pm + pc + pn;
            if (l <= Lsz - 3)           s0 += s;
            if (l >= 1 && l <= Lsz - 2) s1 += s;
            if (l >= 2)                 s2 += s;
            pm = pc; pc = pn;
        }
        S[0][t] = s0; S[1][t] = s1; S[2][t] = s2;
    }
    __syncthreads();
    if (t < Fsz) {
        float a = 0.f;
#pragma unroll
        for (int k = 0; k < 3; k++)
            for (int g = 0; g < Fsz; g++)
                a += S[k][g] * acw[(t * 3 + k) * Fsz + g];
        am[t] = acb[t] + a * (1.f / (float)(Lsz - 2));
    }
    __syncthreads();
    if (t < IDs) {
        float o = fb[t];
        for (int f = 0; f < Fsz; f++) o += am[f] * fw[t * Fsz + f];
        o = fmaxf(o, 0.f);
        int base = side ? (Bsz * 2 * IDs) : 0;
        out[base + (b * 2 + 0) * IDs + t] = o;
    }
    if (t >= 64 && t < 64 + IDs) {
        int i = t - 64;
        if (side == 0) {
            out[(b * 2 + 1) * IDs + i] = iide[(size_t)iids[b] * IDs + i];
        } else {
            out[Bsz * 2 * IDs + (b * 2 + 1) * IDs + i] = uide[(size_t)uids[b] * IDs + i];
        }
    }
}

// ---------------- launch ----------------
extern "C" void kernel_launch(void* const* d_in, const int* in_sizes, int n_in,
                              void* d_out, int out_size) {
    const int*   uids = (const int*)d_in[0];
    const int*   iids = (const int*)d_in[1];
    const int*   udoc = (const int*)d_in[2];
    const int*   idoc = (const int*)d_in[3];
    const float* uemb = (const float*)d_in[4];
    const float* iemb = (const float*)d_in[5];
    const float* wcw  = (const float*)d_in[6];
    const float* wcb  = (const float*)d_in[7];
    const float* udcw = (const float*)d_in[8];
    const float* udcb = (const float*)d_in[9];
    const float* idcw = (const float*)d_in[10];
    const float* idcb = (const float*)d_in[11];
    const float* uacw = (const float*)d_in[12];
    const float* uacb = (const float*)d_in[13];
    const float* iacw = (const float*)d_in[14];
    const float* iacb = (const float*)d_in[15];
    const float* ufw  = (const float*)d_in[16];
    const float* ufb  = (const float*)d_in[17];
    const float* ifw  = (const float*)d_in[18];
    const float* ifb  = (const float*)d_in[19];
    const float* uide = (const float*)d_in[20];
    const float* iide = (const float*)d_in[21];
    float* out = (float*)d_out;

    k_prep<<<(2 * KP * KP + 255) / 256, 256>>>(udcw, idcw);
    dim3 gBL(BL, 2);
    k_gather<<<gBL, 128>>>(udoc, idoc, uemb, iemb, wcw);
    k_gatev<<<(2 * BL + 255) / 256, 256>>>(wcb);
    k_gemm_bf16<<<dim3(250, 5, 2), 256>>>();
    k_comb<<<gBL, 128>>>(udcb, idcb);
    k_att<<<dim3(8, 8, Bsz), 256>>>();
    k_head<<<dim3(Bsz, 2), 128>>>(uacw, uacb, iacw, iacb, ufw, ufb, ifw, ifb,
                                  uids, iids, uide, iide, out);
}

// round 5
// speedup vs baseline: 1.6963x; 1.1625x over previous
#include <cuda_runtime.h>
#include <cuda_bf16.h>

#define Bsz 64
#define Lsz 500
#define Dsz 300
#define Fsz 100
#define IDs 32
#define BL  (Bsz*Lsz)   // 32000
#define KP  320         // padded K (and padded N) for the doc GEMM
#define NK  20          // KP / 16 k-iterations
#define KA  112         // padded F for the attention GEMM (7 x 16)

// ---------------- scratch (static device globals; no allocation) ----------------
__device__ __align__(16) __nv_bfloat16 g_Ah[2][BL*KP];    // A hi split (gathered emb, ungated)
__device__ __align__(16) __nv_bfloat16 g_Al[2][BL*KP];    // A lo split
__device__ __align__(16) __nv_bfloat16 g_Wh[2][KP*KP];    // B hi split, layout [n][k]
__device__ __align__(16) __nv_bfloat16 g_Wl[2][KP*KP];    // B lo split
__device__ float g_dots[2][BL*3];           // word-gate partial dots
__device__ float g_gatev[2][BL];            // sigmoid gate scalar per (b,l)
__device__ float g_C[2][BL*300];            // GEMM out (B*L, 3F), ungated
__device__ float g_ut[2][BL*Fsz];           // conv feature fp32, layout (b,l,f) for k_head
__device__ __align__(16) __nv_bfloat16 g_uth[2][BL*KA];   // ut hi split, [b*L+l][k]
__device__ __align__(16) __nv_bfloat16 g_utl[2][BL*KA];   // ut lo split
__device__ float g_nrm[2][BL];              // per-(b,l) squared norms over F
__device__ float g_att[2][BL];              // attention row/col sums

__device__ __forceinline__ float warpSum(float v) {
#pragma unroll
    for (int o = 16; o; o >>= 1) v += __shfl_down_sync(0xffffffffu, v, o);
    return v;
}

__device__ __forceinline__ unsigned pack_bf(float x0, float x1,
                                            float& r0, float& r1) {
    __nv_bfloat16 h0 = __float2bfloat16(x0);
    __nv_bfloat16 h1 = __float2bfloat16(x1);
    r0 = x0 - __bfloat162float(h0);
    r1 = x1 - __bfloat162float(h1);
    return (unsigned)__bfloat16_as_ushort(h0) |
           ((unsigned)__bfloat16_as_ushort(h1) << 16);
}

__device__ __forceinline__ void ldsm4(unsigned& r0, unsigned& r1,
                                      unsigned& r2, unsigned& r3, unsigned addr) {
    asm volatile("ldmatrix.sync.aligned.m8n8.x4.shared.b16 {%0,%1,%2,%3}, [%4];"
                 : "=r"(r0), "=r"(r1), "=r"(r2), "=r"(r3) : "r"(addr));
}

__device__ __forceinline__ void mma_bf16(float* c, const unsigned* a, const unsigned* b) {
    asm volatile(
        "mma.sync.aligned.m16n8k16.row.col.f32.bf16.bf16.f32 "
        "{%0,%1,%2,%3}, {%4,%5,%6,%7}, {%8,%9}, {%0,%1,%2,%3};\n"
        : "+f"(c[0]), "+f"(c[1]), "+f"(c[2]), "+f"(c[3])
        : "r"(a[0]), "r"(a[1]), "r"(a[2]), "r"(a[3]), "r"(b[0]), "r"(b[1]));
}

__device__ __forceinline__ void cp16(unsigned sdst, const void* gsrc) {
    asm volatile("cp.async.cg.shared.global [%0], [%1], 16;"
                 :: "r"(sdst), "l"(gsrc));
}
__device__ __forceinline__ void cp16z(unsigned sdst, const void* gsrc, bool v) {
    int sz = v ? 16 : 0;
    asm volatile("cp.async.cg.shared.global [%0], [%1], 16, %2;"
                 :: "r"(sdst), "l"(gsrc), "r"(sz));
}
__device__ __forceinline__ void cp_commit() {
    asm volatile("cp.async.commit_group;");
}
template <int N>
__device__ __forceinline__ void cp_wait() {
    asm volatile("cp.async.wait_group %0;" :: "n"(N));
}

// ---------------- K0: repack + bf16-split doc-conv weights -> [n][k] padded ----------------
__global__ void k_prep(const float* __restrict__ uw, const float* __restrict__ iw) {
    int idx = blockIdx.x * 256 + threadIdx.x;
    if (idx >= 2 * KP * KP) return;
    int side = idx / (KP * KP);
    int r = idx - side * KP * KP;
    int n = r / KP, k = r % KP;
    float x = 0.f;
    if (n < 300 && k < 300) {
        int f = n % Fsz, ks = n / Fsz;
        const float* w = side ? iw : uw;
        x = w[(f * 3 + ks) * Dsz + k];
    }
    __nv_bfloat16 h = __float2bfloat16(x);
    float lo = x - __bfloat162float(h);
    g_Wh[side][n * KP + k] = h;
    g_Wl[side][n * KP + k] = __float2bfloat16(lo);
}

// ---------------- K1: gather + word-gate dots + bf16 hi/lo split (ungated) ----------------
__global__ void k_gather(const int* __restrict__ udoc, const int* __restrict__ idoc,
                         const float* __restrict__ uemb, const float* __restrict__ iemb,
                         const float* __restrict__ wc) {
    int side = blockIdx.y;
    int bl = blockIdx.x;
    const int* doc = side ? idoc : udoc;
    const float* emb = side ? iemb : uemb;
    int row = doc[bl];
    const float* e = emb + (size_t)row * Dsz;
    unsigned* ah = reinterpret_cast<unsigned*>(&g_Ah[side][(size_t)bl * KP]);
    unsigned* al = reinterpret_cast<unsigned*>(&g_Al[side][(size_t)bl * KP]);
    float p0 = 0.f, p1 = 0.f, p2 = 0.f;
    for (int p = threadIdx.x; p < KP / 2; p += 128) {
        int d = 2 * p;
        float x0 = 0.f, x1 = 0.f;
        if (d < 300) {
            float2 v = *reinterpret_cast<const float2*>(&e[d]);
            x0 = v.x; x1 = v.y;
            p0 += x0 * wc[d]       + x1 * wc[d + 1];
            p1 += x0 * wc[300 + d] + x1 * wc[301 + d];
            p2 += x0 * wc[600 + d] + x1 * wc[601 + d];
        }
        float l0, l1;
        unsigned hp = pack_bf(x0, x1, l0, l1);
        __nv_bfloat16 lb0 = __float2bfloat16(l0);
        __nv_bfloat16 lb1 = __float2bfloat16(l1);
        ah[p] = hp;
        al[p] = (unsigned)__bfloat16_as_ushort(lb0) |
                ((unsigned)__bfloat16_as_ushort(lb1) << 16);
    }
    __shared__ float sh[3][4];
    p0 = warpSum(p0); p1 = warpSum(p1); p2 = warpSum(p2);
    int lane = threadIdx.x & 31, w = threadIdx.x >> 5;
    if (lane == 0) { sh[0][w] = p0; sh[1][w] = p1; sh[2][w] = p2; }
    __syncthreads();
    if (threadIdx.x == 0) {
        g_dots[side][bl * 3 + 0] = sh[0][0] + sh[0][1] + sh[0][2] + sh[0][3];
        g_dots[side][bl * 3 + 1] = sh[1][0] + sh[1][1] + sh[1][2] + sh[1][3];
        g_dots[side][bl * 3 + 2] = sh[2][0] + sh[2][1] + sh[2][2] + sh[2][3];
    }
}

// ---------------- K2: gate scalar (applied later, in k_comb) ----------------
__global__ void k_gatev(const float* __restrict__ wcb) {
    int idx = blockIdx.x * 256 + threadIdx.x;
    if (idx >= 2 * BL) return;
    int side = idx / BL;
    int bl = idx - side * BL;
    int l = bl % Lsz;
    float g = g_dots[side][bl * 3 + 1] + wcb[0];
    if (l >= 1)       g += g_dots[side][(bl - 1) * 3 + 0];
    if (l <= Lsz - 2) g += g_dots[side][(bl + 1) * 3 + 2];
    g_gatev[side][bl] = 1.f / (1.f + __expf(-g));
}

// ---------------- K3: bf16 tensor-core GEMM (32000x320) @ (320x320), 3-term split ----
// BM=128, BN=64, BK=16, 256 threads (8 warps 4x2), warp tile 32x32.
// cp.async 3-stage pipeline; ldmatrix fragments; conflict-free 48B row stride.
// grid = (n-tiles, m-tiles, side): n fastest for A reuse in L2.
__global__ __launch_bounds__(256, 2) void k_gemm_bf16() {
    const int side = blockIdx.z;
    float* __restrict__ Cm = g_C[side];

    // per stage (bytes): Ah 0..6143 (128 rows x 48B), Al 6144.., Bh 12288.. (64x48), Bl 15360..
    extern __shared__ __align__(16) unsigned char smbuf[];   // 3 x 18432

    const int tid = threadIdx.x;
    const int lane = tid & 31, wid = tid >> 5;
    const int wm = wid >> 1, wn = wid & 1;
    const int n0 = blockIdx.x * 64;
    const int m0 = blockIdx.y * 128;

    const unsigned smem0 = (unsigned)__cvta_generic_to_shared(&smbuf[0]);

    // cp.async mapping: thread does 3 x 16B chunks per stage
    const int arow = tid >> 1, ahalf = tid & 1;
    const char* gA_h = (const char*)&g_Ah[side][((size_t)(m0 + arow)) * KP + ahalf * 8];
    const char* gA_l = (const char*)&g_Al[side][((size_t)(m0 + arow)) * KP + ahalf * 8];
    const unsigned sA_h = smem0 + arow * 48 + ahalf * 16;
    const unsigned sA_l = sA_h + 6144;
    const int brow = (tid & 127) >> 1;
    const __nv_bfloat16* gBarr = (tid < 128) ? g_Wh[side] : g_Wl[side];
    const char* gB = (const char*)&gBarr[((size_t)(n0 + brow)) * KP + ahalf * 8];
    const unsigned sB = smem0 + ((tid < 128) ? 12288u : 15360u) + brow * 48 + ahalf * 16;

    float acc[2][4][4];
#pragma unroll
    for (int i = 0; i < 2; i++)
#pragma unroll
        for (int j = 0; j < 4; j++)
#pragma unroll
            for (int q = 0; q < 4; q++) acc[i][j][q] = 0.f;

    // prologue: stages 0..2
#pragma unroll
    for (int s = 0; s < 3; s++) {
        cp16(sA_h + s * 18432, gA_h + s * 32);
        cp16(sA_l + s * 18432, gA_l + s * 32);
        cp16(sB   + s * 18432, gB   + s * 32);
        cp_commit();
    }

    // fragment addresses (per-stage base added in loop)
    const int l4 = lane & 7, g4 = lane >> 3;
    unsigned aoff[2];
#pragma unroll
    for (int mt = 0; mt < 2; mt++) {
        int rowm = wm * 32 + mt * 16 + (g4 & 1) * 8 + l4;
        int koff = (g4 >> 1) * 8;
        aoff[mt] = smem0 + (rowm * 24 + koff) * 2;
    }
    unsigned boff[2];
#pragma unroll
    for (int ntp = 0; ntp < 2; ntp++) {
        int rown = wn * 32 + ntp * 16 + (g4 >> 1) * 8 + l4;
        int koff = (g4 & 1) * 8;
        boff[ntp] = smem0 + 12288 + (rown * 24 + koff) * 2;
    }

    int stage = 0;
    for (int it = 0; it < NK; it++) {
        const unsigned sbase = stage * 18432u;
        cp_wait<2>();
        __syncthreads();

        unsigned a_h[2][4], a_l[2][4], b_h[2][4], b_l[2][4];
#pragma unroll
        for (int mt = 0; mt < 2; mt++) {
            ldsm4(a_h[mt][0], a_h[mt][1], a_h[mt][2], a_h[mt][3], aoff[mt] + sbase);
            ldsm4(a_l[mt][0], a_l[mt][1], a_l[mt][2], a_l[mt][3], aoff[mt] + sbase + 6144);
        }
#pragma unroll
        for (int ntp = 0; ntp < 2; ntp++) {
            ldsm4(b_h[ntp][0], b_h[ntp][1], b_h[ntp][2], b_h[ntp][3], boff[ntp] + sbase);
            ldsm4(b_l[ntp][0], b_l[ntp][1], b_l[ntp][2], b_l[ntp][3], boff[ntp] + sbase + 3072);
        }
#pragma unroll
        for (int mt = 0; mt < 2; mt++)
#pragma unroll
            for (int nt = 0; nt < 4; nt++) {
                const int bi = nt >> 1, bo = (nt & 1) * 2;
                mma_bf16(acc[mt][nt], a_h[mt], &b_h[bi][bo]);
                mma_bf16(acc[mt][nt], a_h[mt], &b_l[bi][bo]);
                mma_bf16(acc[mt][nt], a_l[mt], &b_h[bi][bo]);
            }
        __syncthreads();
        if (it + 3 < NK) {
            cp16(sA_h + sbase, gA_h + (it + 3) * 32);
            cp16(sA_l + sbase, gA_l + (it + 3) * 32);
            cp16(sB   + sbase, gB   + (it + 3) * 32);
        }
        cp_commit();
        stage = (stage + 1 == 3) ? 0 : stage + 1;
    }

    // epilogue
#pragma unroll
    for (int mt = 0; mt < 2; mt++) {
        int r = m0 + wm * 32 + mt * 16 + (lane >> 2);
#pragma unroll
        for (int nt = 0; nt < 4; nt++) {
            int c = n0 + wn * 32 + nt * 8 + 2 * (lane & 3);
            if (c < 300) {
                Cm[(size_t)r * 300 + c] = acc[mt][nt][0];
                if (c + 1 < 300) Cm[(size_t)r * 300 + c + 1] = acc[mt][nt][1];
                Cm[(size_t)(r + 8) * 300 + c] = acc[mt][nt][2];
                if (c + 1 < 300) Cm[(size_t)(r + 8) * 300 + c + 1] = acc[mt][nt][3];
            }
        }
    }
}

// ---------------- K4: gated shift-add combine -> ut fp32 + bf16 hi/lo, norms ----------------
__global__ void k_comb(const float* __restrict__ udb, const float* __restrict__ idb) {
    int side = blockIdx.y;
    int bl = blockIdx.x;
    int l = bl % Lsz;
    const float* bias = side ? idb : udb;
    const float* Cm = g_C[side];
    const float* gv = g_gatev[side];
    int f = threadIdx.x;
    float val = 0.f;
    if (f < Fsz) {
        val = bias[f] + gv[bl] * Cm[bl * 300 + Fsz + f];
        if (l >= 1)       val += gv[bl - 1] * Cm[(bl - 1) * 300 + f];
        if (l < Lsz - 1)  val += gv[bl + 1] * Cm[(bl + 1) * 300 + 2 * Fsz + f];
        g_ut[side][bl * Fsz + f] = val;
    }
    if (f < KA) {
        __nv_bfloat16 h = __float2bfloat16(val);
        float lo = val - __bfloat162float(h);
        g_uth[side][(size_t)bl * KA + f] = h;
        g_utl[side][(size_t)bl * KA + f] = __float2bfloat16(lo);
    }
    float sq = val * val;
    sq = warpSum(sq);
    __shared__ float sh[4];
    int lane = threadIdx.x & 31, w = threadIdx.x >> 5;
    if (lane == 0) sh[w] = sq;
    __syncthreads();
    if (threadIdx.x == 0) {
        g_nrm[side][bl] = sh[0] + sh[1] + sh[2] + sh[3];
        g_att[side][bl] = 0.f;
    }
}

// ---------------- K5: tensor-core pairwise attention (bf16 3-pass) ----------------
// 64x64 output tile per block; full K (=112) staged in 60KB dynamic smem.
// smem layout: Uh 0, Ul 15360, Vh 30720, Vl 46080; each 64 rows x 240B stride.
__global__ __launch_bounds__(256, 2) void k_att_tc() {
    extern __shared__ __align__(16) unsigned char sm[];
    __shared__ float rsum[64], csum[64];
    const int b = blockIdx.z;
    const int l0 = blockIdx.x * 64, m0 = blockIdx.y * 64;
    const int tid = threadIdx.x;
    const int lane = tid & 31, wid = tid >> 5;
    const int wm2 = wid >> 2, wn2 = wid & 3;        // warp grid 2 x 4 -> warp tile 32(l) x 16(m)
    const unsigned sbase = (unsigned)__cvta_generic_to_shared(&sm[0]);

    if (tid < 64) { rsum[tid] = 0.f; csum[tid] = 0.f; }

    // stage all four tiles: 4 arrays x 64 rows x 14 chunks of 16B
    for (int i = tid; i < 4 * 64 * 14; i += 256) {
        int arr = i / 896;
        int rem = i - arr * 896;
        int r = rem / 14, c = rem - r * 14;
        int vside = arr >> 1;      // 0 = U, 1 = V
        int split = arr & 1;       // 0 = hi, 1 = lo
        int row = (vside ? m0 : l0) + r;
        bool valid = row < Lsz;
        int srow = valid ? row : 0;
        const __nv_bfloat16* src = (split ? g_utl[vside] : g_uth[vside]) +
                                   ((size_t)(b * Lsz + srow)) * KA + c * 8;
        cp16z(sbase + arr * 15360 + r * 240 + c * 16, src, valid);
    }
    cp_commit();
    cp_wait<0>();
    __syncthreads();

    // fragment addresses
    const int l4 = lane & 7, g4 = lane >> 3;
    unsigned aoff[2];
#pragma unroll
    for (int mt = 0; mt < 2; mt++) {
        int rowm = wm2 * 32 + mt * 16 + (g4 & 1) * 8 + l4;
        int koff = (g4 >> 1) * 8;
        aoff[mt] = sbase + (rowm * 120 + koff) * 2;
    }
    unsigned boffv;
    {
        int rown = wn2 * 16 + (g4 >> 1) * 8 + l4;
        int koff = (g4 & 1) * 8;
        boffv = sbase + 30720u + (rown * 120 + koff) * 2;
    }

    float acc[2][2][4];
#pragma unroll
    for (int i = 0; i < 2; i++)
#pragma unroll
        for (int j = 0; j < 2; j++)
#pragma unroll
            for (int q = 0; q < 4; q++) acc[i][j][q] = 0.f;

#pragma unroll
    for (int ck = 0; ck < 7; ck++) {
        const unsigned kb = ck * 32;    // 16 cols * 2B
        unsigned a_h[2][4], a_l[2][4], b_h[4], b_l[4];
#pragma unroll
        for (int mt = 0; mt < 2; mt++) {
            ldsm4(a_h[mt][0], a_h[mt][1], a_h[mt][2], a_h[mt][3], aoff[mt] + kb);
            ldsm4(a_l[mt][0], a_l[mt][1], a_l[mt][2], a_l[mt][3], aoff[mt] + kb + 15360);
        }
        ldsm4(b_h[0], b_h[1], b_h[2], b_h[3], boffv + kb);
        ldsm4(b_l[0], b_l[1], b_l[2], b_l[3], boffv + kb + 15360);
#pragma unroll
        for (int mt = 0; mt < 2; mt++)
#pragma unroll
            for (int nt = 0; nt < 2; nt++) {
                mma_bf16(acc[mt][nt], a_h[mt], &b_h[nt * 2]);
                mma_bf16(acc[mt][nt], a_h[mt], &b_l[nt * 2]);
                mma_bf16(acc[mt][nt], a_l[mt], &b_h[nt * 2]);
            }
    }

    // norms (guarded)
    float nu[2][2], nv[2][2];
#pragma unroll
    for (int mt = 0; mt < 2; mt++)
#pragma unroll
        for (int h = 0; h < 2; h++) {
            int l = l0 + wm2 * 32 + mt * 16 + h * 8 + (lane >> 2);
            nu[mt][h] = (l < Lsz) ? g_nrm[0][b * Lsz + l] : 0.f;
        }
#pragma unroll
    for (int nt = 0; nt < 2; nt++)
#pragma unroll
        for (int cc = 0; cc < 2; cc++) {
            int m = m0 + wn2 * 16 + nt * 8 + 2 * (lane & 3) + cc;
            nv[nt][cc] = (m < Lsz) ? g_nrm[1][b * Lsz + m] : 0.f;
        }

    float rsv[4] = {0, 0, 0, 0}, csv[4] = {0, 0, 0, 0};
#pragma unroll
    for (int mt = 0; mt < 2; mt++)
#pragma unroll
        for (int nt = 0; nt < 2; nt++)
#pragma unroll
            for (int q = 0; q < 4; q++) {
                int h = q >> 1, cc = q & 1;
                int l = l0 + wm2 * 32 + mt * 16 + h * 8 + (lane >> 2);
                int m = m0 + wn2 * 16 + nt * 8 + 2 * (lane & 3) + cc;
                if (l < Lsz && m < Lsz) {
                    float sq = nu[mt][h] + nv[nt][cc] - 2.f * acc[mt][nt][q];
                    float a = 1.f / (1.f + sqrtf(fmaxf(sq, 1e-12f)));
                    rsv[mt * 2 + h] += a;
                    csv[nt * 2 + cc] += a;
                }
            }
#pragma unroll
    for (int q = 0; q < 4; q++) {
        atomicAdd(&rsum[wm2 * 32 + (q >> 1) * 16 + (q & 1) * 8 + (lane >> 2)], rsv[q]);
        atomicAdd(&csum[wn2 * 16 + (q >> 1) * 8 + 2 * (lane & 3) + (q & 1)], csv[q]);
    }
    __syncthreads();
    if (tid < 64) {
        if (l0 + tid < Lsz) atomicAdd(&g_att[0][b * Lsz + l0 + tid], rsum[tid]);
        if (m0 + tid < Lsz) atomicAdd(&g_att[1][b * Lsz + m0 + tid], csum[tid]);
    }
}

// ---------------- K6: pooling (collapsed mean-of-conv) + FC head + id-emb gather ----------------
__global__ void k_head(const float* __restrict__ uacw, const float* __restrict__ uacb,
                       const float* __restrict__ iacw, const float* __restrict__ iacb,
                       const float* __restrict__ ufw,  const float* __restrict__ ufb,
                       const float* __restrict__ ifw,  const float* __restrict__ ifb,
                       const int* __restrict__ uids,   const int* __restrict__ iids,
                       const float* __restrict__ uide, const float* __restrict__ iide,
                       float* __restrict__ out) {
    int b = blockIdx.x;
    int side = blockIdx.y;
    const float* ut  = g_ut[side] + (size_t)b * Lsz * Fsz;
    const float* att = g_att[side] + b * Lsz;
    const float* acw = side ? iacw : uacw;
    const float* acb = side ? iacb : uacb;
    const float* fw  = side ? ifw : ufw;
    const float* fb  = side ? ifb : ufb;
    __shared__ float S[3][Fsz];
    __shared__ float am[Fsz];
    int t = threadIdx.x;

    if (t < Fsz) {
        float s0 = 0.f, s1 = 0.f, s2 = 0.f;
        float pm = 0.f;
        float pc = ut[t] * att[0];
        for (int l = 0; l < Lsz; l++) {
            float pn = (l + 1 < Lsz) ? ut[(l + 1) * Fsz + t] * att[l + 1] : 0.f;
            float s = pm + pc + pn;
            if (l <= Lsz - 3)           s0 += s;
            if (l >= 1 && l <= Lsz - 2) s1 += s;
            if (l >= 2)                 s2 += s;
            pm = pc; pc = pn;
        }
        S[0][t] = s0; S[1][t] = s1; S[2][t] = s2;
    }
    __syncthreads();
    if (t < Fsz) {
        float a = 0.f;
#pragma unroll
        for (int k = 0; k < 3; k++)
            for (int g = 0; g < Fsz; g++)
                a += S[k][g] * acw[(t * 3 + k) * Fsz + g];
        am[t] = acb[t] + a * (1.f / (float)(Lsz - 2));
    }
    __syncthreads();
    if (t < IDs) {
        float o = fb[t];
        for (int f = 0; f < Fsz; f++) o += am[f] * fw[t * Fsz + f];
        o = fmaxf(o, 0.f);
        int base = side ? (Bsz * 2 * IDs) : 0;
        out[base + (b * 2 + 0) * IDs + t] = o;
    }
    if (t >= 64 && t < 64 + IDs) {
        int i = t - 64;
        if (side == 0) {
            out[(b * 2 + 1) * IDs + i] = iide[(size_t)iids[b] * IDs + i];
        } else {
            out[Bsz * 2 * IDs + (b * 2 + 1) * IDs + i] = uide[(size_t)uids[b] * IDs + i];
        }
    }
}

// ---------------- launch ----------------
extern "C" void kernel_launch(void* const* d_in, const int* in_sizes, int n_in,
                              void* d_out, int out_size) {
    const int*   uids = (const int*)d_in[0];
    const int*   iids = (const int*)d_in[1];
    const int*   udoc = (const int*)d_in[2];
    const int*   idoc = (const int*)d_in[3];
    const float* uemb = (const float*)d_in[4];
    const float* iemb = (const float*)d_in[5];
    const float* wcw  = (const float*)d_in[6];
    const float* wcb  = (const float*)d_in[7];
    const float* udcw = (const float*)d_in[8];
    const float* udcb = (const float*)d_in[9];
    const float* idcw = (const float*)d_in[10];
    const float* idcb = (const float*)d_in[11];
    const float* uacw = (const float*)d_in[12];
    const float* uacb = (const float*)d_in[13];
    const float* iacw = (const float*)d_in[14];
    const float* iacb = (const float*)d_in[15];
    const float* ufw  = (const float*)d_in[16];
    const float* ufb  = (const float*)d_in[17];
    const float* ifw  = (const float*)d_in[18];
    const float* ifb  = (const float*)d_in[19];
    const float* uide = (const float*)d_in[20];
    const float* iide = (const float*)d_in[21];
    float* out = (float*)d_out;

    cudaFuncSetAttribute(k_gemm_bf16, cudaFuncAttributeMaxDynamicSharedMemorySize, 3 * 18432);
    cudaFuncSetAttribute(k_att_tc,    cudaFuncAttributeMaxDynamicSharedMemorySize, 4 * 15360);

    k_prep<<<(2 * KP * KP + 255) / 256, 256>>>(udcw, idcw);
    dim3 gBL(BL, 2);
    k_gather<<<gBL, 128>>>(udoc, idoc, uemb, iemb, wcw);
    k_gatev<<<(2 * BL + 255) / 256, 256>>>(wcb);
    k_gemm_bf16<<<dim3(5, 250, 2), 256, 3 * 18432>>>();
    k_comb<<<gBL, 128>>>(udcb, idcb);
    k_att_tc<<<dim3(8, 8, Bsz), 256, 4 * 15360>>>();
    k_head<<<dim3(Bsz, 2), 128>>>(uacw, uacb, iacw, iacb, ufw, ufb, ifw, ifb,
                                  uids, iids, uide, iide, out);
}

// round 7
// speedup vs baseline: 1.7280x; 1.0187x over previous
#include <cuda_runtime.h>
#include <cuda_bf16.h>

#define Bsz 64
#define Lsz 500
#define Dsz 300
#define Fsz 100
#define IDs 32
#define BL  (Bsz*Lsz)   // 32000
#define KP  320         // padded K (and padded N) for the doc GEMM
#define NK  20          // KP / 16 k-iterations
#define KA  112         // padded F for the attention GEMM (7 x 16)

// ---------------- scratch (static device globals; no allocation) ----------------
__device__ __align__(16) __nv_bfloat16 g_Ah[2][BL*KP];    // A hi split (gathered emb, ungated)
__device__ __align__(16) __nv_bfloat16 g_Al[2][BL*KP];    // A lo split
__device__ __align__(16) __nv_bfloat16 g_Wh[2][KP*KP];    // B hi split, layout [n][k]
__device__ __align__(16) __nv_bfloat16 g_Wl[2][KP*KP];    // B lo split
__device__ float g_dots[2][BL*3];
__device__ float g_gatev[2][BL];
__device__ float g_C[2][BL*300];
__device__ float g_ut[2][BL*Fsz];
__device__ __align__(16) __nv_bfloat16 g_uth[2][BL*KA];
__device__ __align__(16) __nv_bfloat16 g_utl[2][BL*KA];
__device__ float g_nrm[2][BL];
__device__ float g_att[2][BL];

__device__ __forceinline__ float warpSum(float v) {
#pragma unroll
    for (int o = 16; o; o >>= 1) v += __shfl_down_sync(0xffffffffu, v, o);
    return v;
}

__device__ __forceinline__ unsigned pack_bf(float x0, float x1, float& r0, float& r1) {
    __nv_bfloat16 h0 = __float2bfloat16(x0);
    __nv_bfloat16 h1 = __float2bfloat16(x1);
    r0 = x0 - __bfloat162float(h0);
    r1 = x1 - __bfloat162float(h1);
    return (unsigned)__bfloat16_as_ushort(h0) | ((unsigned)__bfloat16_as_ushort(h1) << 16);
}

__device__ __forceinline__ void ldsm4(unsigned& r0, unsigned& r1,
                                      unsigned& r2, unsigned& r3, unsigned addr) {
    asm volatile("ldmatrix.sync.aligned.m8n8.x4.shared.b16 {%0,%1,%2,%3}, [%4];"
                 : "=r"(r0), "=r"(r1), "=r"(r2), "=r"(r3) : "r"(addr));
}

__device__ __forceinline__ void mma_bf16(float* c, const unsigned* a, const unsigned* b) {
    asm volatile(
        "mma.sync.aligned.m16n8k16.row.col.f32.bf16.bf16.f32 "
        "{%0,%1,%2,%3}, {%4,%5,%6,%7}, {%8,%9}, {%0,%1,%2,%3};\n"
        : "+f"(c[0]), "+f"(c[1]), "+f"(c[2]), "+f"(c[3])
        : "r"(a[0]), "r"(a[1]), "r"(a[2]), "r"(a[3]), "r"(b[0]), "r"(b[1]));
}

__device__ __forceinline__ void cp16(unsigned sdst, const void* gsrc) {
    asm volatile("cp.async.cg.shared.global [%0], [%1], 16;" :: "r"(sdst), "l"(gsrc));
}
__device__ __forceinline__ void cp16z(unsigned sdst, const void* gsrc, bool v) {
    int sz = v ? 16 : 0;
    asm volatile("cp.async.cg.shared.global [%0], [%1], 16, %2;" :: "r"(sdst), "l"(gsrc), "r"(sz));
}
__device__ __forceinline__ void cp_commit() { asm volatile("cp.async.commit_group;"); }
template <int N>
__device__ __forceinline__ void cp_wait() { asm volatile("cp.async.wait_group %0;" :: "n"(N)); }

__device__ __forceinline__ unsigned s2u(const void* p) {
    unsigned a;
    asm("{ .reg .u64 t; cvta.to.shared.u64 t, %1; cvt.u32.u64 %0, t; }" : "=r"(a) : "l"(p));
    return a;
}

// ---------------- K0: repack + bf16-split doc-conv weights -> [n][k] padded ----------------
__global__ void k_prep(const float* __restrict__ uw, const float* __restrict__ iw) {
    int idx = blockIdx.x * 256 + threadIdx.x;
    if (idx >= 2 * KP * KP) return;
    int side = idx / (KP * KP);
    int r = idx - side * KP * KP;
    int n = r / KP, k = r % KP;
    float x = 0.f;
    if (n < 300 && k < 300) {
        int f = n % Fsz, ks = n / Fsz;
        const float* w = side ? iw : uw;
        x = w[(f * 3 + ks) * Dsz + k];
    }
    __nv_bfloat16 h = __float2bfloat16(x);
    float lo = x - __bfloat162float(h);
    g_Wh[side][n * KP + k] = h;
    g_Wl[side][n * KP + k] = __float2bfloat16(lo);
}

// ---------------- K1: gather + word-gate dots + bf16 hi/lo split (ungated) ----------------
__global__ void k_gather(const int* __restrict__ udoc, const int* __restrict__ idoc,
                         const float* __restrict__ uemb, const float* __restrict__ iemb,
                         const float* __restrict__ wc) {
    int side = blockIdx.y;
    int bl = blockIdx.x;
    const int* doc = side ? idoc : udoc;
    const float* emb = side ? iemb : uemb;
    int row = doc[bl];
    const float* e = emb + (size_t)row * Dsz;
    unsigned* ah = reinterpret_cast<unsigned*>(&g_Ah[side][(size_t)bl * KP]);
    unsigned* al = reinterpret_cast<unsigned*>(&g_Al[side][(size_t)bl * KP]);
    float p0 = 0.f, p1 = 0.f, p2 = 0.f;
    for (int p = threadIdx.x; p < KP / 2; p += 128) {
        int d = 2 * p;
        float x0 = 0.f, x1 = 0.f;
        if (d < 300) {
            float2 v = *reinterpret_cast<const float2*>(&e[d]);
            x0 = v.x; x1 = v.y;
            p0 += x0 * wc[d]       + x1 * wc[d + 1];
            p1 += x0 * wc[300 + d] + x1 * wc[301 + d];
            p2 += x0 * wc[600 + d] + x1 * wc[601 + d];
        }
        float l0, l1;
        unsigned hp = pack_bf(x0, x1, l0, l1);
        __nv_bfloat16 lb0 = __float2bfloat16(l0);
        __nv_bfloat16 lb1 = __float2bfloat16(l1);
        ah[p] = hp;
        al[p] = (unsigned)__bfloat16_as_ushort(lb0) | ((unsigned)__bfloat16_as_ushort(lb1) << 16);
    }
    __shared__ float sh[3][4];
    p0 = warpSum(p0); p1 = warpSum(p1); p2 = warpSum(p2);
    int lane = threadIdx.x & 31, w = threadIdx.x >> 5;
    if (lane == 0) { sh[0][w] = p0; sh[1][w] = p1; sh[2][w] = p2; }
    __syncthreads();
    if (threadIdx.x == 0) {
        g_dots[side][bl * 3 + 0] = sh[0][0] + sh[0][1] + sh[0][2] + sh[0][3];
        g_dots[side][bl * 3 + 1] = sh[1][0] + sh[1][1] + sh[1][2] + sh[1][3];
        g_dots[side][bl * 3 + 2] = sh[2][0] + sh[2][1] + sh[2][2] + sh[2][3];
    }
}

// ---------------- K2: gate scalar (applied later, in k_comb) ----------------
__global__ void k_gatev(const float* __restrict__ wcb) {
    int idx = blockIdx.x * 256 + threadIdx.x;
    if (idx >= 2 * BL) return;
    int side = idx / BL;
    int bl = idx - side * BL;
    int l = bl % Lsz;
    float g = g_dots[side][bl * 3 + 1] + wcb[0];
    if (l >= 1)       g += g_dots[side][(bl - 1) * 3 + 0];
    if (l <= Lsz - 2) g += g_dots[side][(bl + 1) * 3 + 2];
    g_gatev[side][bl] = 1.f / (1.f + __expf(-g));
}

// ---------------- K3: bf16 mma GEMM (32000x320)@(320x320), 3-term split ----------------
// BM=128, BN=64, BK=16, 256 threads (8 warps 4x2), warp tile 32x32.
// 4-stage cp.async pipeline, ONE __syncthreads per k-iter (loads issued pre-compute).
__global__ __launch_bounds__(256, 2) void k_gemm_bf16() {
    const int side = blockIdx.z;
    float* __restrict__ Cm = g_C[side];

    // per stage (bytes): Ah 0..6143 (128 rows x 48B), Al 6144.., Bh 12288.. (64x48), Bl 15360..
    extern __shared__ __align__(16) unsigned char smbuf[];   // 4 x 18432

    const int tid = threadIdx.x;
    const int lane = tid & 31, wid = tid >> 5;
    const int wm = wid >> 1, wn = wid & 1;
    const int n0 = blockIdx.x * 64;
    const int m0 = blockIdx.y * 128;

    const unsigned smem0 = s2u(&smbuf[0]);

    // cp.async mapping: thread does 3 x 16B chunks per stage
    const int arow = tid >> 1, ahalf = tid & 1;
    const char* gA_h = (const char*)&g_Ah[side][((size_t)(m0 + arow)) * KP + ahalf * 8];
    const char* gA_l = (const char*)&g_Al[side][((size_t)(m0 + arow)) * KP + ahalf * 8];
    const unsigned sA_h = smem0 + arow * 48 + ahalf * 16;
    const unsigned sA_l = sA_h + 6144;
    const int brow = (tid & 127) >> 1;
    const __nv_bfloat16* gBarr = (tid < 128) ? g_Wh[side] : g_Wl[side];
    const char* gB = (const char*)&gBarr[((size_t)(n0 + brow)) * KP + ahalf * 8];
    const unsigned sB = smem0 + ((tid < 128) ? 12288u : 15360u) + brow * 48 + ahalf * 16;

    float acc[2][4][4];
#pragma unroll
    for (int i = 0; i < 2; i++)
#pragma unroll
        for (int j = 0; j < 4; j++)
#pragma unroll
            for (int q = 0; q < 4; q++) acc[i][j][q] = 0.f;

    // prologue: stages 0..2 (chunks 0..2)
#pragma unroll
    for (int s = 0; s < 3; s++) {
        cp16(sA_h + s * 18432u, gA_h + s * 32);
        cp16(sA_l + s * 18432u, gA_l + s * 32);
        cp16(sB   + s * 18432u, gB   + s * 32);
        cp_commit();
    }

    // fragment addresses (per-stage base added in loop)
    const int l4 = lane & 7, g4 = lane >> 3;
    unsigned aoff[2];
#pragma unroll
    for (int mt = 0; mt < 2; mt++) {
        int rowm = wm * 32 + mt * 16 + (g4 & 1) * 8 + l4;
        int koff = (g4 >> 1) * 8;
        aoff[mt] = smem0 + (rowm * 24 + koff) * 2;
    }
    unsigned boff[2];
#pragma unroll
    for (int ntp = 0; ntp < 2; ntp++) {
        int rown = wn * 32 + ntp * 16 + (g4 >> 1) * 8 + l4;
        int koff = (g4 & 1) * 8;
        boff[ntp] = smem0 + 12288 + (rown * 24 + koff) * 2;
    }

    for (int it = 0; it < NK; it++) {
        const unsigned sbase = (unsigned)(it & 3) * 18432u;
        if (it < NK - 3) cp_wait<2>(); else cp_wait<0>();
        __syncthreads();   // single barrier per iter: stage it ready AND stage it+3 free

        // issue next chunk's loads immediately (overlaps with mma below)
        if (it + 3 < NK) {
            const unsigned nb = (unsigned)((it + 3) & 3) * 18432u;
            cp16(sA_h + nb, gA_h + (it + 3) * 32);
            cp16(sA_l + nb, gA_l + (it + 3) * 32);
            cp16(sB   + nb, gB   + (it + 3) * 32);
            cp_commit();
        }

        unsigned a_h[2][4], a_l[2][4], b_h[2][4], b_l[2][4];
#pragma unroll
        for (int mt = 0; mt < 2; mt++) {
            ldsm4(a_h[mt][0], a_h[mt][1], a_h[mt][2], a_h[mt][3], aoff[mt] + sbase);
            ldsm4(a_l[mt][0], a_l[mt][1], a_l[mt][2], a_l[mt][3], aoff[mt] + sbase + 6144);
        }
#pragma unroll
        for (int ntp = 0; ntp < 2; ntp++) {
            ldsm4(b_h[ntp][0], b_h[ntp][1], b_h[ntp][2], b_h[ntp][3], boff[ntp] + sbase);
            ldsm4(b_l[ntp][0], b_l[ntp][1], b_l[ntp][2], b_l[ntp][3], boff[ntp] + sbase + 3072);
        }
#pragma unroll
        for (int mt = 0; mt < 2; mt++)
#pragma unroll
            for (int nt = 0; nt < 4; nt++) {
                const int bi = nt >> 1, bo = (nt & 1) * 2;
                mma_bf16(acc[mt][nt], a_h[mt], &b_h[bi][bo]);
                mma_bf16(acc[mt][nt], a_h[mt], &b_l[bi][bo]);
                mma_bf16(acc[mt][nt], a_l[mt], &b_h[bi][bo]);
            }
    }

    // epilogue
#pragma unroll
    for (int mt = 0; mt < 2; mt++) {
        int r = m0 + wm * 32 + mt * 16 + (lane >> 2);
#pragma unroll
        for (int nt = 0; nt < 4; nt++) {
            int c = n0 + wn * 32 + nt * 8 + 2 * (lane & 3);
            if (c < 300) {
                Cm[(size_t)r * 300 + c] = acc[mt][nt][0];
                if (c + 1 < 300) Cm[(size_t)r * 300 + c + 1] = acc[mt][nt][1];
                Cm[(size_t)(r + 8) * 300 + c] = acc[mt][nt][2];
                if (c + 1 < 300) Cm[(size_t)(r + 8) * 300 + c + 1] = acc[mt][nt][3];
            }
        }
    }
}

// ---------------- K4: gated shift-add combine -> ut fp32 + bf16 hi/lo, norms ----------------
__global__ void k_comb(const float* __restrict__ udb, const float* __restrict__ idb) {
    int side = blockIdx.y;
    int bl = blockIdx.x;
    int l = bl % Lsz;
    const float* bias = side ? idb : udb;
    const float* Cm = g_C[side];
    const float* gv = g_gatev[side];
    int f = threadIdx.x;
    float val = 0.f;
    if (f < Fsz) {
        val = bias[f] + gv[bl] * Cm[bl * 300 + Fsz + f];
        if (l >= 1)       val += gv[bl - 1] * Cm[(bl - 1) * 300 + f];
        if (l < Lsz - 1)  val += gv[bl + 1] * Cm[(bl + 1) * 300 + 2 * Fsz + f];
        g_ut[side][bl * Fsz + f] = val;
    }
    if (f < KA) {
        __nv_bfloat16 h = __float2bfloat16(val);
        float lo = val - __bfloat162float(h);
        g_uth[side][(size_t)bl * KA + f] = h;
        g_utl[side][(size_t)bl * KA + f] = __float2bfloat16(lo);
    }
    float sq = val * val;
    sq = warpSum(sq);
    __shared__ float sh[4];
    int lane = threadIdx.x & 31, w = threadIdx.x >> 5;
    if (lane == 0) sh[w] = sq;
    __syncthreads();
    if (threadIdx.x == 0) {
        g_nrm[side][bl] = sh[0] + sh[1] + sh[2] + sh[3];
        g_att[side][bl] = 0.f;
    }
}

// ---------------- K5: tensor-core pairwise attention (bf16 3-pass) ----------------
__global__ __launch_bounds__(256, 2) void k_att_tc() {
    extern __shared__ __align__(16) unsigned char sm[];
    __shared__ float rsum[64], csum[64];
    const int b = blockIdx.z;
    const int l0 = blockIdx.x * 64, m0 = blockIdx.y * 64;
    const int tid = threadIdx.x;
    const int lane = tid & 31, wid = tid >> 5;
    const int wm2 = wid >> 2, wn2 = wid & 3;
    const unsigned sbase = s2u(&sm[0]);

    if (tid < 64) { rsum[tid] = 0.f; csum[tid] = 0.f; }

    for (int i = tid; i < 4 * 64 * 14; i += 256) {
        int arr = i / 896;
        int rem = i - arr * 896;
        int r = rem / 14, c = rem - r * 14;
        int vside = arr >> 1;
        int split = arr & 1;
        int row = (vside ? m0 : l0) + r;
        bool valid = row < Lsz;
        int srow = valid ? row : 0;
        const __nv_bfloat16* src = (split ? g_utl[vside] : g_uth[vside]) +
                                   ((size_t)(b * Lsz + srow)) * KA + c * 8;
        cp16z(sbase + arr * 15360 + r * 240 + c * 16, src, valid);
    }
    cp_commit();
    cp_wait<0>();
    __syncthreads();

    const int l4 = lane & 7, g4 = lane >> 3;
    unsigned aoff[2];
#pragma unroll
    for (int mt = 0; mt < 2; mt++) {
        int rowm = wm2 * 32 + mt * 16 + (g4 & 1) * 8 + l4;
        int koff = (g4 >> 1) * 8;
        aoff[mt] = sbase + (rowm * 120 + koff) * 2;
    }
    unsigned boffv;
    {
        int rown = wn2 * 16 + (g4 >> 1) * 8 + l4;
        int koff = (g4 & 1) * 8;
        boffv = sbase + 30720u + (rown * 120 + koff) * 2;
    }

    float acc[2][2][4];
#pragma unroll
    for (int i = 0; i < 2; i++)
#pragma unroll
        for (int j = 0; j < 2; j++)
#pragma unroll
            for (int q = 0; q < 4; q++) acc[i][j][q] = 0.f;

#pragma unroll
    for (int ck = 0; ck < 7; ck++) {
        const unsigned kb = ck * 32;
        unsigned a_h[2][4], a_l[2][4], b_h[4], b_l[4];
#pragma unroll
        for (int mt = 0; mt < 2; mt++) {
            ldsm4(a_h[mt][0], a_h[mt][1], a_h[mt][2], a_h[mt][3], aoff[mt] + kb);
            ldsm4(a_l[mt][0], a_l[mt][1], a_l[mt][2], a_l[mt][3], aoff[mt] + kb + 15360);
        }
        ldsm4(b_h[0], b_h[1], b_h[2], b_h[3], boffv + kb);
        ldsm4(b_l[0], b_l[1], b_l[2], b_l[3], boffv + kb + 15360);
#pragma unroll
        for (int mt = 0; mt < 2; mt++)
#pragma unroll
            for (int nt = 0; nt < 2; nt++) {
                mma_bf16(acc[mt][nt], a_h[mt], &b_h[nt * 2]);
                mma_bf16(acc[mt][nt], a_h[mt], &b_l[nt * 2]);
                mma_bf16(acc[mt][nt], a_l[mt], &b_h[nt * 2]);
            }
    }

    float nu[2][2], nv[2][2];
#pragma unroll
    for (int mt = 0; mt < 2; mt++)
#pragma unroll
        for (int h = 0; h < 2; h++) {
            int l = l0 + wm2 * 32 + mt * 16 + h * 8 + (lane >> 2);
            nu[mt][h] = (l < Lsz) ? g_nrm[0][b * Lsz + l] : 0.f;
        }
#pragma unroll
    for (int nt = 0; nt < 2; nt++)
#pragma unroll
        for (int cc = 0; cc < 2; cc++) {
            int m = m0 + wn2 * 16 + nt * 8 + 2 * (lane & 3) + cc;
            nv[nt][cc] = (m < Lsz) ? g_nrm[1][b * Lsz + m] : 0.f;
        }

    float rsv[4] = {0, 0, 0, 0}, csv[4] = {0, 0, 0, 0};
#pragma unroll
    for (int mt = 0; mt < 2; mt++)
#pragma unroll
        for (int nt = 0; nt < 2; nt++)
#pragma unroll
            for (int q = 0; q < 4; q++) {
                int h = q >> 1, cc = q & 1;
                int l = l0 + wm2 * 32 + mt * 16 + h * 8 + (lane >> 2);
                int m = m0 + wn2 * 16 + nt * 8 + 2 * (lane & 3) + cc;
                if (l < Lsz && m < Lsz) {
                    float sq = nu[mt][h] + nv[nt][cc] - 2.f * acc[mt][nt][q];
                    float a = 1.f / (1.f + sqrtf(fmaxf(sq, 1e-12f)));
                    rsv[mt * 2 + h] += a;
                    csv[nt * 2 + cc] += a;
                }
            }
#pragma unroll
    for (int q = 0; q < 4; q++) {
        atomicAdd(&rsum[wm2 * 32 + (q >> 1) * 16 + (q & 1) * 8 + (lane >> 2)], rsv[q]);
        atomicAdd(&csum[wn2 * 16 + (q >> 1) * 8 + 2 * (lane & 3) + (q & 1)], csv[q]);
    }
    __syncthreads();
    if (tid < 64) {
        if (l0 + tid < Lsz) atomicAdd(&g_att[0][b * Lsz + l0 + tid], rsum[tid]);
        if (m0 + tid < Lsz) atomicAdd(&g_att[1][b * Lsz + m0 + tid], csum[tid]);
    }
}

// ---------------- K6: pooling + FC head + id-emb gather ----------------
__global__ void k_head(const float* __restrict__ uacw, const float* __restrict__ uacb,
                       const float* __restrict__ iacw, const float* __restrict__ iacb,
                       const float* __restrict__ ufw,  const float* __restrict__ ufb,
                       const float* __restrict__ ifw,  const float* __restrict__ ifb,
                       const int* __restrict__ uids,   const int* __restrict__ iids,
                       const float* __restrict__ uide, const float* __restrict__ iide,
                       float* __restrict__ out) {
    int b = blockIdx.x;
    int side = blockIdx.y;
    const float* ut  = g_ut[side] + (size_t)b * Lsz * Fsz;
    const float* att = g_att[side] + b * Lsz;
    const float* acw = side ? iacw : uacw;
    const float* acb = side ? iacb : uacb;
    const float* fw  = side ? ifw : ufw;
    const float* fb  = side ? ifb : ufb;
    __shared__ float S[3][Fsz];
    __shared__ float am[Fsz];
    int t = threadIdx.x;

    if (t < Fsz) {
        float s0 = 0.f, s1 = 0.f, s2 = 0.f;
        float pm = 0.f;
        float pc = ut[t] * att[0];
        for (int l = 0; l < Lsz; l++) {
            float pn = (l + 1 < Lsz) ? ut[(l + 1) * Fsz + t] * att[l + 1] : 0.f;
            float s = pm + pc + pn;
            if (l <= Lsz - 3)           s0 += s;
            if (l >= 1 && l <= Lsz - 2) s1 += s;
            if (l >= 2)                 s2 += s;
            pm = pc; pc = pn;
        }
        S[0][t] = s0; S[1][t] = s1; S[2][t] = s2;
    }
    __syncthreads();
    if (t < Fsz) {
        float a = 0.f;
#pragma unroll
        for (int k = 0; k < 3; k++)
            for (int g = 0; g < Fsz; g++)
                a += S[k][g] * acw[(t * 3 + k) * Fsz + g];
        am[t] = acb[t] + a * (1.f / (float)(Lsz - 2));
    }
    __syncthreads();
    if (t < IDs) {
        float o = fb[t];
        for (int f = 0; f < Fsz; f++) o += am[f] * fw[t * Fsz + f];
        o = fmaxf(o, 0.f);
        int base = side ? (Bsz * 2 * IDs) : 0;
        out[base + (b * 2 + 0) * IDs + t] = o;
    }
    if (t >= 64 && t < 64 + IDs) {
        int i = t - 64;
        if (side == 0) {
            out[(b * 2 + 1) * IDs + i] = iide[(size_t)iids[b] * IDs + i];
        } else {
            out[Bsz * 2 * IDs + (b * 2 + 1) * IDs + i] = uide[(size_t)uids[b] * IDs + i];
        }
    }
}

// ---------------- launch ----------------
extern "C" void kernel_launch(void* const* d_in, const int* in_sizes, int n_in,
                              void* d_out, int out_size) {
    const int*   uids = (const int*)d_in[0];
    const int*   iids = (const int*)d_in[1];
    const int*   udoc = (const int*)d_in[2];
    const int*   idoc = (const int*)d_in[3];
    const float* uemb = (const float*)d_in[4];
    const float* iemb = (const float*)d_in[5];
    const float* wcw  = (const float*)d_in[6];
    const float* wcb  = (const float*)d_in[7];
    const float* udcw = (const float*)d_in[8];
    const float* udcb = (const float*)d_in[9];
    const float* idcw = (const float*)d_in[10];
    const float* idcb = (const float*)d_in[11];
    const float* uacw = (const float*)d_in[12];
    const float* uacb = (const float*)d_in[13];
    const float* iacw = (const float*)d_in[14];
    const float* iacb = (const float*)d_in[15];
    const float* ufw  = (const float*)d_in[16];
    const float* ufb  = (const float*)d_in[17];
    const float* ifw  = (const float*)d_in[18];
    const float* ifb  = (const float*)d_in[19];
    const float* uide = (const float*)d_in[20];
    const float* iide = (const float*)d_in[21];
    float* out = (float*)d_out;

    cudaFuncSetAttribute(k_gemm_bf16, cudaFuncAttributeMaxDynamicSharedMemorySize, 4 * 18432);
    cudaFuncSetAttribute(k_att_tc,    cudaFuncAttributeMaxDynamicSharedMemorySize, 4 * 15360);

    k_prep<<<(2 * KP * KP + 255) / 256, 256>>>(udcw, idcw);
    dim3 gBL(BL, 2);
    k_gather<<<gBL, 128>>>(udoc, idoc, uemb, iemb, wcw);
    k_gatev<<<(2 * BL + 255) / 256, 256>>>(wcb);
    k_gemm_bf16<<<dim3(5, 250, 2), 256, 4 * 18432>>>();
    k_comb<<<gBL, 128>>>(udcb, idcb);
    k_att_tc<<<dim3(8, 8, Bsz), 256, 4 * 15360>>>();
    k_head<<<dim3(Bsz, 2), 128>>>(uacw, uacb, iacw, iacb, ufw, ufb, ifw, ifb,
                                  uids, iids, uide, iide, out);
}